// round 9
// baseline (speedup 1.0000x reference)
#include <cuda_runtime.h>
#include <cuda_bf16.h>
#include <cstdint>

#define NB 8192
#define NK 8192
#define ND 512
#define NM (8192ULL * 8192ULL)
#define GK 1536

// ---------------- static device scratch ----------------
__device__ float  g_za[NM];
__device__ float  g_zaT[NM];
__device__ float  g_Dm[NM];
__device__ __nv_bfloat16 g_Xe[8192ULL * GK];  // [x1|x1|x2]
__device__ __nv_bfloat16 g_Ce[8192ULL * GK];  // [c1|c2|c1]
__device__ float  g_nx[NB];
__device__ float  g_nc[NK];
__device__ double g_r[NB];
__device__ double g_c[NK];
__device__ float  g_zr[NB];
__device__ float  g_zc[NK];
__device__ double g_Spart[16384];
__device__ double g_S;
__device__ unsigned g_maxbits;
__device__ unsigned g_minbits;
__device__ float  g_midf;
__device__ float  g_rangef;
__device__ int    g_idx[NB];

__device__ __forceinline__ unsigned encf(float f) {
    unsigned u = __float_as_uint(f);
    return (u & 0x80000000u) ? ~u : (u | 0x80000000u);
}
__device__ __forceinline__ float decf(unsigned u) {
    return (u & 0x80000000u) ? __uint_as_float(u & 0x7FFFFFFFu) : __uint_as_float(~u);
}
__device__ __forceinline__ float log2_of_double(double v) {
    int e; double m = frexp(v, &e);
    return (float)e + log2f((float)m);
}
__device__ __forceinline__ uint32_t smem_u32(const void* p) {
    uint32_t a;
    asm("{ .reg .u64 t; cvta.to.shared.u64 t, %1; cvt.u32.u64 %0, t; }" : "=r"(a) : "l"(p));
    return a;
}
__device__ __forceinline__ void cpa16(uint32_t s, const void* g) {
    asm volatile("cp.async.cg.shared.global [%0], [%1], 16;" :: "r"(s), "l"(g) : "memory");
}
#define CPA_COMMIT() asm volatile("cp.async.commit_group;" ::: "memory")
template <int N> __device__ __forceinline__ void cpa_wait() {
    asm volatile("cp.async.wait_group %0;" :: "n"(N) : "memory");
}
__device__ __forceinline__ void ldsm4(uint32_t* r, uint32_t addr) {
    asm volatile("ldmatrix.sync.aligned.m8n8.x4.shared.b16 {%0,%1,%2,%3}, [%4];"
        : "=r"(r[0]), "=r"(r[1]), "=r"(r[2]), "=r"(r[3]) : "r"(addr));
}
__device__ __forceinline__ void mma16816(float* d, const uint32_t* a, uint32_t b0, uint32_t b1) {
    asm volatile("mma.sync.aligned.m16n8k16.row.col.f32.bf16.bf16.f32 "
        "{%0,%1,%2,%3}, {%4,%5,%6,%7}, {%8,%9}, {%0,%1,%2,%3};"
        : "+f"(d[0]), "+f"(d[1]), "+f"(d[2]), "+f"(d[3])
        : "r"(a[0]), "r"(a[1]), "r"(a[2]), "r"(a[3]), "r"(b0), "r"(b1));
}

// ---------------- reset ----------------
__global__ void reset_kernel() {
    if (threadIdx.x == 0) { g_maxbits = 0u; g_minbits = 0xFFFFFFFFu; }
}

// ---------------- row norms ----------------
__global__ __launch_bounds__(128) void norms_kernel(const float* __restrict__ X,
                                                    const float* __restrict__ C) {
    int row = blockIdx.x;
    const float* p = (blockIdx.y == 0 ? X : C) + (size_t)row * ND;
    float4 v = ((const float4*)p)[threadIdx.x];
    double s = (double)v.x * v.x + (double)v.y * v.y + (double)v.z * v.z + (double)v.w * v.w;
    for (int o = 16; o; o >>= 1) s += __shfl_down_sync(0xffffffffu, s, o);
    __shared__ double sm[4];
    if ((threadIdx.x & 31) == 0) sm[threadIdx.x >> 5] = s;
    __syncthreads();
    if (threadIdx.x == 0) {
        double t = (sm[0] + sm[1]) + (sm[2] + sm[3]);
        if (blockIdx.y == 0) g_nx[row] = (float)t; else g_nc[row] = (float)t;
    }
}

// ---------------- split-bf16 prep ----------------
__global__ __launch_bounds__(256) void split_kernel(const float* __restrict__ X,
                                                    const float* __restrict__ C) {
    size_t idx = (size_t)blockIdx.x * 256 + threadIdx.x;
    size_t row = idx >> 9, k = idx & 511;
    {
        float x = X[idx];
        __nv_bfloat16 b1 = __float2bfloat16(x);
        __nv_bfloat16 b2 = __float2bfloat16(x - __bfloat162float(b1));
        __nv_bfloat16* d = g_Xe + row * GK + k;
        d[0] = b1; d[512] = b1; d[1024] = b2;
    }
    {
        float c = C[idx];
        __nv_bfloat16 b1 = __float2bfloat16(c);
        __nv_bfloat16 b2 = __float2bfloat16(c - __bfloat162float(b1));
        __nv_bfloat16* d = g_Ce + row * GK + k;
        d[0] = b1; d[512] = b2; d[1024] = b1;
    }
}

// ---------------- tensor-core GEMM: 3-stage cp.async pipeline ----------------
#define SPITCH 40                      // bf16 per smem row (80 B)
#define STAGE_BYTES 20480              // A(10240) + B(10240) per stage
#define NCH (GK / 32)                  // 48 K-chunks

__global__ __launch_bounds__(256) void mma_gemm_kernel() {
    extern __shared__ __align__(16) char gsm[];
    const int tid = threadIdx.x;
    const int lane = tid & 31, wid = tid >> 5;
    const int wm = wid & 3, wn = wid >> 2;
    const int bi = blockIdx.y << 7, bj = blockIdx.x << 7;
    const uint32_t sbase = smem_u32(gsm);
    const __nv_bfloat16* Ag = g_Xe + (size_t)bi * GK;
    const __nv_bfloat16* Bg = g_Ce + (size_t)bj * GK;

    float acc[2][8][4];
#pragma unroll
    for (int t = 0; t < 2; t++)
#pragma unroll
        for (int u = 0; u < 8; u++)
#pragma unroll
            for (int v = 0; v < 4; v++) acc[t][u][v] = 0.f;

#define LOAD_CHUNK(c, st)                                                           \
    {                                                                               \
        _Pragma("unroll")                                                           \
        for (int t = 0; t < 2; t++) {                                               \
            int s = tid + (t << 8);                                                 \
            int r = s >> 2, sg = (s & 3) << 3;                                      \
            uint32_t so = (uint32_t)(st) * STAGE_BYTES + r * (SPITCH * 2) + sg * 2; \
            const size_t go = (size_t)r * GK + (size_t)(c) * 32 + sg;               \
            cpa16(sbase + so, Ag + go);                                             \
            cpa16(sbase + so + 10240u, Bg + go);                                    \
        }                                                                           \
    }

    LOAD_CHUNK(0, 0); CPA_COMMIT();
    LOAD_CHUNK(1, 1); CPA_COMMIT();

    const uint32_t aRowOff = (uint32_t)(wm * 32 + (lane & 15)) * (SPITCH * 2);
    const uint32_t aColOff = (uint32_t)((lane >> 4) << 3) * 2;
    const uint32_t bRowBase = (uint32_t)(wn * 64 + (lane & 7) + (((lane >> 4) & 1) << 3));
    const uint32_t bColOff = (uint32_t)(((lane >> 3) & 1) << 3) * 2;

    int bc = 0, bl = 2;
    for (int c = 0; c < NCH; c++) {
        cpa_wait<1>();
        __syncthreads();
        if (c + 2 < NCH) LOAD_CHUNK(c + 2, bl);
        CPA_COMMIT();
        uint32_t abase = sbase + (uint32_t)bc * STAGE_BYTES;
        uint32_t bbase = abase + 10240u;
#pragma unroll
        for (int kk = 0; kk < 2; kk++) {
            uint32_t a[2][4], b[4][4];
#pragma unroll
            for (int t = 0; t < 2; t++)
                ldsm4(a[t], abase + aRowOff + (uint32_t)(t * 16) * (SPITCH * 2)
                            + aColOff + (uint32_t)(kk * 16) * 2);
#pragma unroll
            for (int p = 0; p < 4; p++)
                ldsm4(b[p], bbase + (bRowBase + p * 16) * (SPITCH * 2)
                            + bColOff + (uint32_t)(kk * 16) * 2);
#pragma unroll
            for (int t = 0; t < 2; t++)
#pragma unroll
                for (int u = 0; u < 8; u++)
                    mma16816(acc[t][u], a[t], b[u >> 1][(u & 1) << 1], b[u >> 1][((u & 1) << 1) + 1]);
        }
        bc = (bc == 2) ? 0 : bc + 1;
        bl = (bl == 2) ? 0 : bl + 1;
    }

    float lmx = -3.4e38f, lmn = 3.4e38f;
#pragma unroll
    for (int t = 0; t < 2; t++) {
        int r0 = bi + wm * 32 + t * 16 + (lane >> 2);
        float nx0 = g_nx[r0], nx1 = g_nx[r0 + 8];
#pragma unroll
        for (int u = 0; u < 8; u++) {
            int col = bj + wn * 64 + u * 8 + ((lane & 3) << 1);
            float nc0 = g_nc[col], nc1 = g_nc[col + 1];
            float d00 = (nx0 + nc0) - 2.0f * acc[t][u][0];
            float d01 = (nx0 + nc1) - 2.0f * acc[t][u][1];
            float d10 = (nx1 + nc0) - 2.0f * acc[t][u][2];
            float d11 = (nx1 + nc1) - 2.0f * acc[t][u][3];
            *(float2*)(g_Dm + (size_t)r0 * NK + col) = make_float2(d00, d01);
            *(float2*)(g_Dm + (size_t)(r0 + 8) * NK + col) = make_float2(d10, d11);
            lmx = fmaxf(lmx, fmaxf(fmaxf(d00, d01), fmaxf(d10, d11)));
            lmn = fminf(lmn, fminf(fminf(d00, d01), fminf(d10, d11)));
        }
    }
    for (int o = 16; o; o >>= 1) {
        lmx = fmaxf(lmx, __shfl_down_sync(0xffffffffu, lmx, o));
        lmn = fminf(lmn, __shfl_down_sync(0xffffffffu, lmn, o));
    }
    __shared__ float smx[8], smn[8];
    if (lane == 0) { smx[wid] = lmx; smn[wid] = lmn; }
    __syncthreads();
    if (tid == 0) {
#pragma unroll
        for (int w = 1; w < 8; w++) { lmx = fmaxf(lmx, smx[w]); lmn = fminf(lmn, smn[w]); }
        atomicMax(&g_maxbits, encf(lmx));
        atomicMin(&g_minbits, encf(lmn));
    }
}

__global__ void finalize_kernel() {
    float mx = decf(g_maxbits), mn = decf(g_minbits);
    float mid = (mx + mn) * 0.5f;
    g_midf = mid;
    g_rangef = (mx - mid) + 1e-8f;
}

// ---------------- fill: za + zaT + S partials ----------------
__global__ __launch_bounds__(256) void fill_kernel() {
    __shared__ float tile[64][65];
    __shared__ float sred[16];
    __shared__ float smb;
    const float midf = g_midf;
    const float rangef = g_rangef;
    const float cfh = -480.89834696298781f;
    const int tid = threadIdx.x;
    const int lane = tid & 31, warp = tid >> 5;
    const size_t i0 = (size_t)blockIdx.y * 64;
    const size_t j0 = (size_t)blockIdx.x * 64;
    const int r0 = tid >> 4;
    const int c4 = (tid & 15) << 2;

    float va[16];
    float mx = -3.4e38f;
#pragma unroll
    for (int k = 0; k < 4; k++) {
        int r = r0 + (k << 4);
        float4 d = *(const float4*)(g_Dm + (i0 + r) * NK + j0 + c4);
        float z0 = ((d.x - midf) / rangef) * cfh;
        float z1 = ((d.y - midf) / rangef) * cfh;
        float z2 = ((d.z - midf) / rangef) * cfh;
        float z3 = ((d.w - midf) / rangef) * cfh;
        va[k * 4 + 0] = z0; va[k * 4 + 1] = z1; va[k * 4 + 2] = z2; va[k * 4 + 3] = z3;
        tile[r][c4 + 0] = z0; tile[r][c4 + 1] = z1; tile[r][c4 + 2] = z2; tile[r][c4 + 3] = z3;
        *(float4*)(g_za + (i0 + r) * NK + j0 + c4) = make_float4(z0, z1, z2, z3);
        mx = fmaxf(mx, fmaxf(fmaxf(z0, z1), fmaxf(z2, z3)));
    }
    for (int o = 16; o; o >>= 1) mx = fmaxf(mx, __shfl_down_sync(0xffffffffu, mx, o));
    if (lane == 0) sred[warp] = mx;
    __syncthreads();
    if (tid == 0) {
        float m = sred[0];
#pragma unroll
        for (int w = 1; w < 8; w++) m = fmaxf(m, sred[w]);
        smb = floorf(m);
    }
    __syncthreads();
    const float mbf = smb;
    float s = 0.f;
#pragma unroll
    for (int k = 0; k < 16; k++) s += exp2f(va[k] - mbf);
    for (int o = 16; o; o >>= 1) s += __shfl_down_sync(0xffffffffu, s, o);
    if (lane == 0) sred[8 + warp] = s;
    __syncthreads();
    if (tid == 0) {
        float tot = 0.f;
#pragma unroll
        for (int w = 0; w < 8; w++) tot += sred[8 + w];
        g_Spart[blockIdx.y * 128 + blockIdx.x] = ldexp((double)tot, (int)mbf);
    }
#pragma unroll
    for (int k = 0; k < 4; k++) {
        int r = r0 + (k << 4);
        float4 v = make_float4(tile[c4 + 0][r], tile[c4 + 1][r], tile[c4 + 2][r], tile[c4 + 3][r]);
        *(float4*)(g_zaT + (j0 + r) * NK + i0 + c4) = v;
    }
}

__global__ __launch_bounds__(1024) void reduceS_kernel() {
    int tid = threadIdx.x;
    double s = 0.0;
#pragma unroll
    for (int k = 0; k < 16; k++) s += g_Spart[tid + k * 1024];
    __shared__ double sm[1024];
    sm[tid] = s;
    __syncthreads();
    for (int o = 512; o; o >>= 1) {
        if (tid < o) sm[tid] += sm[tid + o];
        __syncthreads();
    }
    if (tid == 0) g_S = sm[0];
}

__global__ void init_rc_kernel() {
    int t = blockIdx.x * blockDim.x + threadIdx.x;
    double S = g_S;
    if (t < NB) { g_r[t] = 1.0 / S; g_zr[t] = -log2_of_double(S); }
    if (t < NK) { g_c[t] = 1.0;     g_zc[t] = 0.0f; }
}

// ---------------- Sinkhorn pass: warp-per-row, register double-buffered ----------------
__device__ __forceinline__ void proc_chunk(float4* buf, const float4* __restrict__ c4,
                                           int ch, int lane, float& M, float& E) {
    float cmx = -3.4e38f;
#pragma unroll
    for (int v = 0; v < 8; v++) {
        int j4 = (ch << 8) + (v << 5) + lane;
        float4 c = __ldg(&c4[j4]);
        buf[v].x += c.x; buf[v].y += c.y; buf[v].z += c.z; buf[v].w += c.w;
        cmx = fmaxf(cmx, fmaxf(fmaxf(buf[v].x, buf[v].y), fmaxf(buf[v].z, buf[v].w)));
    }
    float s0 = 0.f, s1 = 0.f, s2 = 0.f, s3 = 0.f;
#pragma unroll
    for (int v = 0; v < 8; v++) {
        s0 += exp2f(buf[v].x - cmx);
        s1 += exp2f(buf[v].y - cmx);
        s2 += exp2f(buf[v].z - cmx);
        s3 += exp2f(buf[v].w - cmx);
    }
    float s = (s0 + s1) + (s2 + s3);
    if (cmx > E) { M = M * exp2f(E - cmx) + s; E = cmx; }
    else         { M += s * exp2f(cmx - E); }
}

__global__ __launch_bounds__(256) void pass_kernel(int dir) {
    const float* __restrict__ ZA   = dir ? g_zaT : g_za;
    const float* __restrict__ zo   = dir ? g_zr  : g_zc;
    double* __restrict__      vec  = dir ? g_c   : g_r;
    float* __restrict__       zvec = dir ? g_zc  : g_zr;

    const int lane = threadIdx.x & 31;
    const int i = (blockIdx.x << 3) + (threadIdx.x >> 5);
    const float4* a4 = (const float4*)(ZA + (size_t)i * NK);
    const float4* c4 = (const float4*)zo;

    float4 bufA[8], bufB[8];
#pragma unroll
    for (int v = 0; v < 8; v++) bufA[v] = a4[(v << 5) + lane];

    float M = 0.f, E = -3.4e38f;
#pragma unroll
    for (int ch = 0; ch < 8; ch += 2) {
        if (ch + 1 < 8) {
#pragma unroll
            for (int v = 0; v < 8; v++) bufB[v] = a4[((ch + 1) << 8) + (v << 5) + lane];
        }
        proc_chunk(bufA, c4, ch, lane, M, E);
        if (ch + 2 < 8) {
#pragma unroll
            for (int v = 0; v < 8; v++) bufA[v] = a4[((ch + 2) << 8) + (v << 5) + lane];
        }
        if (ch + 1 < 8) proc_chunk(bufB, c4, ch + 1, lane, M, E);
    }
    for (int o = 16; o; o >>= 1) {
        float oe = __shfl_down_sync(0xffffffffu, E, o);
        float om = __shfl_down_sync(0xffffffffu, M, o);
        if (oe > E) { M = M * exp2f(E - oe) + om; E = oe; }
        else        { M += om * exp2f(oe - E); }
    }
    if (lane == 0) {
        float Ei = floorf(E);
        double y = ldexp((double)(M * exp2f(E - Ei)), (int)Ei);
        double v = vec[i];
        double vn = v / ((v * y) + 1e-8) / 8192.0;
        vec[i] = vn;
        zvec[i] = log2_of_double(vn);
    }
}

// ---------------- probs + argmax: warp-per-row ----------------
__global__ __launch_bounds__(256) void probs_kernel(float* __restrict__ out_probs,
                                                    float* __restrict__ out_idx) {
    const int lane = threadIdx.x & 31;
    const int i = (blockIdx.x << 3) + (threadIdx.x >> 5);
    const float lR = log2_of_double(8192.0 * g_r[i]);
    const float4* a4 = (const float4*)(g_za + (size_t)i * NK);
    const float4* c4 = (const float4*)g_zc;
    float4* o4 = (float4*)(out_probs + (size_t)i * NK);

    float best = -3.4e38f; int bj = 0x7FFFFFFF;
#pragma unroll 4
    for (int v = 0; v < 64; v++) {
        int j4 = (v << 5) + lane;
        float4 a = a4[j4];
        float4 c = __ldg(&c4[j4]);
        float t0 = a.x + c.x, t1 = a.y + c.y, t2 = a.z + c.z, t3 = a.w + c.w;
        o4[j4] = make_float4(exp2f(t0 + lR), exp2f(t1 + lR), exp2f(t2 + lR), exp2f(t3 + lR));
        int jb = j4 << 2;
        if (t0 > best) { best = t0; bj = jb; }
        if (t1 > best) { best = t1; bj = jb + 1; }
        if (t2 > best) { best = t2; bj = jb + 2; }
        if (t3 > best) { best = t3; bj = jb + 3; }
    }
    for (int o = 16; o; o >>= 1) {
        float ov = __shfl_down_sync(0xffffffffu, best, o);
        int oi = __shfl_down_sync(0xffffffffu, bj, o);
        if (ov > best || (ov == best && oi < bj)) { best = ov; bj = oi; }
    }
    if (lane == 0) { g_idx[i] = bj; out_idx[i] = (float)bj; }
}

// ---------------- epilogue ----------------
__global__ __launch_bounds__(128) void epilogue_kernel(const float* __restrict__ X,
                                                       const float* __restrict__ C,
                                                       float* __restrict__ qh,
                                                       float* __restrict__ qs,
                                                       float* __restrict__ loss) {
    int i = blockIdx.x;
    int idx = g_idx[i];
    const float4* cb = (const float4*)(C + (size_t)idx * ND);
    const float4* xr = (const float4*)(X + (size_t)i * ND);
    float4* oh = (float4*)(qh + (size_t)i * ND);
    float4* os = (float4*)(qs + (size_t)i * ND);
    int t = threadIdx.x;
    float4 c4 = cb[t];
    float4 x4 = xr[t];
    oh[t] = c4;
    float dx = c4.x - x4.x, dy = c4.y - x4.y, dz = c4.z - x4.z, dw = c4.w - x4.w;
    os[t] = make_float4(dx + x4.x, dy + x4.y, dz + x4.z, dw + x4.w);
    double s = (double)dx * dx + (double)dy * dy + (double)dz * dz + (double)dw * dw;
    for (int o = 16; o; o >>= 1) s += __shfl_down_sync(0xffffffffu, s, o);
    __shared__ double sm[4];
    if ((t & 31) == 0) sm[t >> 5] = s;
    __syncthreads();
    if (t == 0) {
        double tot = (sm[0] + sm[1]) + (sm[2] + sm[3]);
        float cl = (float)(tot / (double)ND);
        loss[i] = cl + 0.25f * cl;
    }
}

// ---------------- launch ----------------
extern "C" void kernel_launch(void* const* d_in, const int* in_sizes, int n_in,
                              void* d_out, int out_size) {
    const float* X = (const float*)d_in[0];
    const float* C = (const float*)d_in[1];
    float* out = (float*)d_out;
    float* o_qh    = out;
    float* o_qs    = out + (size_t)NB * ND;
    float* o_idx   = out + 2ULL * NB * ND;
    float* o_probs = o_idx + NB;
    float* o_loss  = o_probs + NM;

    cudaFuncSetAttribute(mma_gemm_kernel, cudaFuncAttributeMaxDynamicSharedMemorySize,
                         3 * STAGE_BYTES);

    reset_kernel<<<1, 32>>>();
    norms_kernel<<<dim3(NB, 2), 128>>>(X, C);
    split_kernel<<<16384, 256>>>(X, C);
    mma_gemm_kernel<<<dim3(64, 64), 256, 3 * STAGE_BYTES>>>();
    finalize_kernel<<<1, 1>>>();
    fill_kernel<<<dim3(128, 128), 256>>>();
    reduceS_kernel<<<1, 1024>>>();
    init_rc_kernel<<<32, 256>>>();
    for (int it = 0; it < 50; it++) {
        pass_kernel<<<1024, 256>>>(0);
        pass_kernel<<<1024, 256>>>(1);
    }
    probs_kernel<<<1024, 256>>>(o_probs, o_idx);
    epilogue_kernel<<<NB, 128>>>(X, C, o_qh, o_qs, o_loss);
}

// round 10
// speedup vs baseline: 1.0003x; 1.0003x over previous
#include <cuda_runtime.h>
#include <cuda_bf16.h>
#include <cstdint>

#define NB 8192
#define NK 8192
#define ND 512
#define NM (8192ULL * 8192ULL)
#define GK 1536

// ---------------- static device scratch ----------------
__device__ float  g_Dm[NM];          // d2, row-major (256 MB)
__device__ float  g_DmT[NM];         // d2 transposed (256 MB)
__device__ __nv_bfloat16 g_Xe[8192ULL * GK];  // [x1|x1|x2]
__device__ __nv_bfloat16 g_Ce[8192ULL * GK];  // [c1|c2|c1]
__device__ float  g_nx[NB];
__device__ float  g_nc[NK];
__device__ double g_r[NB];
__device__ double g_c[NK];
__device__ float  g_zr[NB];          // log2(r) + k2
__device__ float  g_zc[NK];          // log2(c) + k2
__device__ double g_Spart[16384];
__device__ double g_S;
__device__ unsigned g_maxbits;
__device__ unsigned g_minbits;
__device__ float  g_k1;
__device__ float  g_k2;
__device__ int    g_idx[NB];

__device__ __forceinline__ unsigned encf(float f) {
    unsigned u = __float_as_uint(f);
    return (u & 0x80000000u) ? ~u : (u | 0x80000000u);
}
__device__ __forceinline__ float decf(unsigned u) {
    return (u & 0x80000000u) ? __uint_as_float(u & 0x7FFFFFFFu) : __uint_as_float(~u);
}
__device__ __forceinline__ float log2_of_double(double v) {
    int e; double m = frexp(v, &e);
    return (float)e + log2f((float)m);
}
__device__ __forceinline__ uint32_t smem_u32(const void* p) {
    uint32_t a;
    asm("{ .reg .u64 t; cvta.to.shared.u64 t, %1; cvt.u32.u64 %0, t; }" : "=r"(a) : "l"(p));
    return a;
}
__device__ __forceinline__ void cpa16(uint32_t s, const void* g) {
    asm volatile("cp.async.cg.shared.global [%0], [%1], 16;" :: "r"(s), "l"(g) : "memory");
}
#define CPA_COMMIT() asm volatile("cp.async.commit_group;" ::: "memory")
template <int N> __device__ __forceinline__ void cpa_wait() {
    asm volatile("cp.async.wait_group %0;" :: "n"(N) : "memory");
}
__device__ __forceinline__ void ldsm4(uint32_t* r, uint32_t addr) {
    asm volatile("ldmatrix.sync.aligned.m8n8.x4.shared.b16 {%0,%1,%2,%3}, [%4];"
        : "=r"(r[0]), "=r"(r[1]), "=r"(r[2]), "=r"(r[3]) : "r"(addr));
}
__device__ __forceinline__ void mma16816(float* d, const uint32_t* a, uint32_t b0, uint32_t b1) {
    asm volatile("mma.sync.aligned.m16n8k16.row.col.f32.bf16.bf16.f32 "
        "{%0,%1,%2,%3}, {%4,%5,%6,%7}, {%8,%9}, {%0,%1,%2,%3};"
        : "+f"(d[0]), "+f"(d[1]), "+f"(d[2]), "+f"(d[3])
        : "r"(a[0]), "r"(a[1]), "r"(a[2]), "r"(a[3]), "r"(b0), "r"(b1));
}

// ---------------- reset ----------------
__global__ void reset_kernel() {
    if (threadIdx.x == 0) { g_maxbits = 0u; g_minbits = 0xFFFFFFFFu; }
}

// ---------------- row norms ----------------
__global__ __launch_bounds__(128) void norms_kernel(const float* __restrict__ X,
                                                    const float* __restrict__ C) {
    int row = blockIdx.x;
    const float* p = (blockIdx.y == 0 ? X : C) + (size_t)row * ND;
    float4 v = ((const float4*)p)[threadIdx.x];
    double s = (double)v.x * v.x + (double)v.y * v.y + (double)v.z * v.z + (double)v.w * v.w;
    for (int o = 16; o; o >>= 1) s += __shfl_down_sync(0xffffffffu, s, o);
    __shared__ double sm[4];
    if ((threadIdx.x & 31) == 0) sm[threadIdx.x >> 5] = s;
    __syncthreads();
    if (threadIdx.x == 0) {
        double t = (sm[0] + sm[1]) + (sm[2] + sm[3]);
        if (blockIdx.y == 0) g_nx[row] = (float)t; else g_nc[row] = (float)t;
    }
}

// ---------------- split-bf16 prep ----------------
__global__ __launch_bounds__(256) void split_kernel(const float* __restrict__ X,
                                                    const float* __restrict__ C) {
    size_t idx = (size_t)blockIdx.x * 256 + threadIdx.x;
    size_t row = idx >> 9, k = idx & 511;
    {
        float x = X[idx];
        __nv_bfloat16 b1 = __float2bfloat16(x);
        __nv_bfloat16 b2 = __float2bfloat16(x - __bfloat162float(b1));
        __nv_bfloat16* d = g_Xe + row * GK + k;
        d[0] = b1; d[512] = b1; d[1024] = b2;
    }
    {
        float c = C[idx];
        __nv_bfloat16 b1 = __float2bfloat16(c);
        __nv_bfloat16 b2 = __float2bfloat16(c - __bfloat162float(b1));
        __nv_bfloat16* d = g_Ce + row * GK + k;
        d[0] = b1; d[512] = b2; d[1024] = b1;
    }
}

// ---------------- tensor-core GEMM: 4-stage cp.async, compile-time stages ----------------
#define SPITCH 40                      // bf16 per smem row (80 B)
#define STAGE_BYTES 20480              // A(10240)+B(10240) per stage
#define NCH (GK / 32)                  // 48 chunks

__global__ __launch_bounds__(256) void mma_gemm_kernel() {
    extern __shared__ __align__(16) char gsm[];
    const int tid = threadIdx.x;
    const int lane = tid & 31, wid = tid >> 5;
    const int wm = wid & 3, wn = wid >> 2;
    const int bi = blockIdx.y << 7, bj = blockIdx.x << 7;
    const uint32_t sbase = smem_u32(gsm);
    const __nv_bfloat16* Ag = g_Xe + (size_t)bi * GK;
    const __nv_bfloat16* Bg = g_Ce + (size_t)bj * GK;

    float acc[2][8][4];
#pragma unroll
    for (int t = 0; t < 2; t++)
#pragma unroll
        for (int u = 0; u < 8; u++)
#pragma unroll
            for (int v = 0; v < 4; v++) acc[t][u][v] = 0.f;

#define LOAD_CHUNK(c, st)                                                             \
    {                                                                                 \
        _Pragma("unroll")                                                             \
        for (int t = 0; t < 2; t++) {                                                 \
            int s_ = tid + (t << 8);                                                  \
            int r_ = s_ >> 2, sg = (s_ & 3) << 3;                                     \
            uint32_t so = (uint32_t)(st) * STAGE_BYTES + r_ * (SPITCH * 2) + sg * 2;  \
            const size_t go = (size_t)r_ * GK + (size_t)(c) * 32 + sg;                \
            cpa16(sbase + so, Ag + go);                                               \
            cpa16(sbase + so + 10240u, Bg + go);                                      \
        }                                                                             \
    }

    LOAD_CHUNK(0, 0); CPA_COMMIT();
    LOAD_CHUNK(1, 1); CPA_COMMIT();
    LOAD_CHUNK(2, 2); CPA_COMMIT();

    const uint32_t aRowOff = (uint32_t)(wm * 32 + (lane & 15)) * (SPITCH * 2);
    const uint32_t aColOff = (uint32_t)((lane >> 4) << 3) * 2;
    const uint32_t bRowBase = (uint32_t)(wn * 64 + (lane & 7) + (((lane >> 4) & 1) << 3));
    const uint32_t bColOff = (uint32_t)(((lane >> 3) & 1) << 3) * 2;

#define STEP(c, s)                                                                    \
    {                                                                                 \
        cpa_wait<2>();                                                                \
        __syncthreads();                                                              \
        if ((c) + 3 < NCH) LOAD_CHUNK((c) + 3, ((s) + 3) & 3);                        \
        CPA_COMMIT();                                                                 \
        const uint32_t abase = sbase + (uint32_t)(s) * STAGE_BYTES;                   \
        const uint32_t bbase = abase + 10240u;                                        \
        _Pragma("unroll")                                                             \
        for (int kk = 0; kk < 2; kk++) {                                              \
            uint32_t a[2][4], b[4][4];                                                \
            _Pragma("unroll")                                                         \
            for (int t = 0; t < 2; t++)                                               \
                ldsm4(a[t], abase + aRowOff + (uint32_t)(t * 16) * (SPITCH * 2)       \
                            + aColOff + (uint32_t)(kk * 16) * 2);                     \
            _Pragma("unroll")                                                         \
            for (int p = 0; p < 4; p++)                                               \
                ldsm4(b[p], bbase + (bRowBase + p * 16) * (SPITCH * 2)                \
                            + bColOff + (uint32_t)(kk * 16) * 2);                     \
            _Pragma("unroll")                                                         \
            for (int t = 0; t < 2; t++)                                               \
                _Pragma("unroll")                                                     \
                for (int u = 0; u < 8; u++)                                           \
                    mma16816(acc[t][u], a[t], b[u >> 1][(u & 1) << 1],                \
                             b[u >> 1][((u & 1) << 1) + 1]);                          \
        }                                                                             \
    }

    for (int ci = 0; ci < NCH; ci += 4) {
        STEP(ci + 0, 0);
        STEP(ci + 1, 1);
        STEP(ci + 2, 2);
        STEP(ci + 3, 3);
    }

    float lmx = -3.4e38f, lmn = 3.4e38f;
#pragma unroll
    for (int t = 0; t < 2; t++) {
        int r0 = bi + wm * 32 + t * 16 + (lane >> 2);
        float nx0 = g_nx[r0], nx1 = g_nx[r0 + 8];
#pragma unroll
        for (int u = 0; u < 8; u++) {
            int col = bj + wn * 64 + u * 8 + ((lane & 3) << 1);
            float nc0 = g_nc[col], nc1 = g_nc[col + 1];
            float d00 = (nx0 + nc0) - 2.0f * acc[t][u][0];
            float d01 = (nx0 + nc1) - 2.0f * acc[t][u][1];
            float d10 = (nx1 + nc0) - 2.0f * acc[t][u][2];
            float d11 = (nx1 + nc1) - 2.0f * acc[t][u][3];
            *(float2*)(g_Dm + (size_t)r0 * NK + col) = make_float2(d00, d01);
            *(float2*)(g_Dm + (size_t)(r0 + 8) * NK + col) = make_float2(d10, d11);
            lmx = fmaxf(lmx, fmaxf(fmaxf(d00, d01), fmaxf(d10, d11)));
            lmn = fminf(lmn, fminf(fminf(d00, d01), fminf(d10, d11)));
        }
    }
    for (int o = 16; o; o >>= 1) {
        lmx = fmaxf(lmx, __shfl_down_sync(0xffffffffu, lmx, o));
        lmn = fminf(lmn, __shfl_down_sync(0xffffffffu, lmn, o));
    }
    __shared__ float smx[8], smn[8];
    if (lane == 0) { smx[wid] = lmx; smn[wid] = lmn; }
    __syncthreads();
    if (tid == 0) {
#pragma unroll
        for (int w = 1; w < 8; w++) { lmx = fmaxf(lmx, smx[w]); lmn = fminf(lmn, smn[w]); }
        atomicMax(&g_maxbits, encf(lmx));
        atomicMin(&g_minbits, encf(lmn));
    }
}

__global__ void finalize_kernel() {
    float mx = decf(g_maxbits), mn = decf(g_minbits);
    float mid = (mx + mn) * 0.5f;
    float range = (mx - mid) + 1e-8f;
    float k1 = -480.89834696298781f / range;   // cfh / range
    g_k1 = k1;
    g_k2 = -mid * k1;
}

// ---------------- transpose Dm -> DmT + S partials ----------------
__global__ __launch_bounds__(256) void transpose_kernel() {
    __shared__ float tile[64][65];
    __shared__ float sred[16];
    __shared__ float smb;
    const float k1 = g_k1, k2 = g_k2;
    const int tid = threadIdx.x;
    const int lane = tid & 31, warp = tid >> 5;
    const size_t i0 = (size_t)blockIdx.y * 64;
    const size_t j0 = (size_t)blockIdx.x * 64;
    const int r0 = tid >> 4;
    const int c4 = (tid & 15) << 2;

    float va[16];
    float mx = -3.4e38f;
#pragma unroll
    for (int k = 0; k < 4; k++) {
        int r = r0 + (k << 4);
        float4 d = *(const float4*)(g_Dm + (i0 + r) * NK + j0 + c4);
        tile[r][c4 + 0] = d.x; tile[r][c4 + 1] = d.y;
        tile[r][c4 + 2] = d.z; tile[r][c4 + 3] = d.w;
        float z0 = fmaf(d.x, k1, k2), z1 = fmaf(d.y, k1, k2);
        float z2 = fmaf(d.z, k1, k2), z3 = fmaf(d.w, k1, k2);
        va[k * 4 + 0] = z0; va[k * 4 + 1] = z1; va[k * 4 + 2] = z2; va[k * 4 + 3] = z3;
        mx = fmaxf(mx, fmaxf(fmaxf(z0, z1), fmaxf(z2, z3)));
    }
    for (int o = 16; o; o >>= 1) mx = fmaxf(mx, __shfl_down_sync(0xffffffffu, mx, o));
    if (lane == 0) sred[warp] = mx;
    __syncthreads();
    if (tid == 0) {
        float m = sred[0];
#pragma unroll
        for (int w = 1; w < 8; w++) m = fmaxf(m, sred[w]);
        smb = floorf(m);
    }
    __syncthreads();
    const float mbf = smb;
    float s = 0.f;
#pragma unroll
    for (int k = 0; k < 16; k++) s += exp2f(va[k] - mbf);
    for (int o = 16; o; o >>= 1) s += __shfl_down_sync(0xffffffffu, s, o);
    if (lane == 0) sred[8 + warp] = s;
    __syncthreads();
    if (tid == 0) {
        float tot = 0.f;
#pragma unroll
        for (int w = 0; w < 8; w++) tot += sred[8 + w];
        g_Spart[blockIdx.y * 128 + blockIdx.x] = ldexp((double)tot, (int)mbf);
    }
#pragma unroll
    for (int k = 0; k < 4; k++) {
        int r = r0 + (k << 4);
        float4 v = make_float4(tile[c4 + 0][r], tile[c4 + 1][r], tile[c4 + 2][r], tile[c4 + 3][r]);
        *(float4*)(g_DmT + (j0 + r) * NK + i0 + c4) = v;
    }
}

__global__ __launch_bounds__(1024) void reduceS_kernel() {
    int tid = threadIdx.x;
    double s = 0.0;
#pragma unroll
    for (int k = 0; k < 16; k++) s += g_Spart[tid + k * 1024];
    __shared__ double sm[1024];
    sm[tid] = s;
    __syncthreads();
    for (int o = 512; o; o >>= 1) {
        if (tid < o) sm[tid] += sm[tid + o];
        __syncthreads();
    }
    if (tid == 0) g_S = sm[0];
}

__global__ void init_rc_kernel() {
    int t = blockIdx.x * blockDim.x + threadIdx.x;
    double S = g_S;
    float k2 = g_k2;
    if (t < NB) { g_r[t] = 1.0 / S; g_zr[t] = k2 - log2_of_double(S); }
    if (t < NK) { g_c[t] = 1.0;     g_zc[t] = k2; }
}

// ---------------- Sinkhorn pass: warp-per-row over Dm/DmT with affine ----------------
__global__ __launch_bounds__(256) void pass_kernel(int dir) {
    const float* __restrict__ ZA   = dir ? g_DmT : g_Dm;
    const float* __restrict__ zo   = dir ? g_zr  : g_zc;
    double* __restrict__      vec  = dir ? g_c   : g_r;
    float* __restrict__       zvec = dir ? g_zc  : g_zr;
    const float k1 = g_k1, k2 = g_k2;

    const int lane = threadIdx.x & 31;
    const int i = (blockIdx.x << 3) + (threadIdx.x >> 5);
    const float4* a4 = (const float4*)(ZA + (size_t)i * NK);
    const float4* c4 = (const float4*)zo;

    float M = 0.f, E = -3.4e38f;
#pragma unroll 1
    for (int ch = 0; ch < 8; ch++) {
        float t[32];
        float cmx = -3.4e38f;
#pragma unroll
        for (int v = 0; v < 8; v++) {
            int j4 = (ch << 8) + (v << 5) + lane;
            float4 a = a4[j4];
            float4 c = __ldg(&c4[j4]);
            float t0 = fmaf(a.x, k1, c.x), t1 = fmaf(a.y, k1, c.y);
            float t2 = fmaf(a.z, k1, c.z), t3 = fmaf(a.w, k1, c.w);
            t[v * 4 + 0] = t0; t[v * 4 + 1] = t1; t[v * 4 + 2] = t2; t[v * 4 + 3] = t3;
            cmx = fmaxf(cmx, fmaxf(fmaxf(t0, t1), fmaxf(t2, t3)));
        }
        float s0 = 0.f, s1 = 0.f, s2 = 0.f, s3 = 0.f;
#pragma unroll
        for (int v = 0; v < 8; v++) {
            s0 += exp2f(t[v * 4 + 0] - cmx);
            s1 += exp2f(t[v * 4 + 1] - cmx);
            s2 += exp2f(t[v * 4 + 2] - cmx);
            s3 += exp2f(t[v * 4 + 3] - cmx);
        }
        float s = (s0 + s1) + (s2 + s3);
        if (cmx > E) { M = M * exp2f(E - cmx) + s; E = cmx; }
        else         { M += s * exp2f(cmx - E); }
    }
    for (int o = 16; o; o >>= 1) {
        float oe = __shfl_down_sync(0xffffffffu, E, o);
        float om = __shfl_down_sync(0xffffffffu, M, o);
        if (oe > E) { M = M * exp2f(E - oe) + om; E = oe; }
        else        { M += om * exp2f(oe - E); }
    }
    if (lane == 0) {
        float Ei = floorf(E);
        double y = ldexp((double)(M * exp2f(E - Ei)), (int)Ei);
        double v = vec[i];
        double vn = v / ((v * y) + 1e-8) / 8192.0;
        vec[i] = vn;
        zvec[i] = k2 + log2_of_double(vn);
    }
}

// ---------------- probs + argmax: warp-per-row ----------------
__global__ __launch_bounds__(256) void probs_kernel(float* __restrict__ out_probs,
                                                    float* __restrict__ out_idx) {
    const int lane = threadIdx.x & 31;
    const int i = (blockIdx.x << 3) + (threadIdx.x >> 5);
    const float k1 = g_k1;
    const float lR = log2_of_double(8192.0 * g_r[i]);
    const float4* a4 = (const float4*)(g_Dm + (size_t)i * NK);
    const float4* c4 = (const float4*)g_zc;
    float4* o4 = (float4*)(out_probs + (size_t)i * NK);

    float best = -3.4e38f; int bj = 0x7FFFFFFF;
#pragma unroll 4
    for (int v = 0; v < 64; v++) {
        int j4 = (v << 5) + lane;
        float4 a = a4[j4];
        float4 c = __ldg(&c4[j4]);
        float t0 = fmaf(a.x, k1, c.x), t1 = fmaf(a.y, k1, c.y);
        float t2 = fmaf(a.z, k1, c.z), t3 = fmaf(a.w, k1, c.w);
        o4[j4] = make_float4(exp2f(t0 + lR), exp2f(t1 + lR), exp2f(t2 + lR), exp2f(t3 + lR));
        int jb = j4 << 2;
        if (t0 > best) { best = t0; bj = jb; }
        if (t1 > best) { best = t1; bj = jb + 1; }
        if (t2 > best) { best = t2; bj = jb + 2; }
        if (t3 > best) { best = t3; bj = jb + 3; }
    }
    for (int o = 16; o; o >>= 1) {
        float ov = __shfl_down_sync(0xffffffffu, best, o);
        int oi = __shfl_down_sync(0xffffffffu, bj, o);
        if (ov > best || (ov == best && oi < bj)) { best = ov; bj = oi; }
    }
    if (lane == 0) { g_idx[i] = bj; out_idx[i] = (float)bj; }
}

// ---------------- epilogue ----------------
__global__ __launch_bounds__(128) void epilogue_kernel(const float* __restrict__ X,
                                                       const float* __restrict__ C,
                                                       float* __restrict__ qh,
                                                       float* __restrict__ qs,
                                                       float* __restrict__ loss) {
    int i = blockIdx.x;
    int idx = g_idx[i];
    const float4* cb = (const float4*)(C + (size_t)idx * ND);
    const float4* xr = (const float4*)(X + (size_t)i * ND);
    float4* oh = (float4*)(qh + (size_t)i * ND);
    float4* os = (float4*)(qs + (size_t)i * ND);
    int t = threadIdx.x;
    float4 c4 = cb[t];
    float4 x4 = xr[t];
    oh[t] = c4;
    float dx = c4.x - x4.x, dy = c4.y - x4.y, dz = c4.z - x4.z, dw = c4.w - x4.w;
    os[t] = make_float4(dx + x4.x, dy + x4.y, dz + x4.z, dw + x4.w);
    double s = (double)dx * dx + (double)dy * dy + (double)dz * dz + (double)dw * dw;
    for (int o = 16; o; o >>= 1) s += __shfl_down_sync(0xffffffffu, s, o);
    __shared__ double sm[4];
    if ((t & 31) == 0) sm[t >> 5] = s;
    __syncthreads();
    if (t == 0) {
        double tot = (sm[0] + sm[1]) + (sm[2] + sm[3]);
        float cl = (float)(tot / (double)ND);
        loss[i] = cl + 0.25f * cl;
    }
}

// ---------------- launch ----------------
extern "C" void kernel_launch(void* const* d_in, const int* in_sizes, int n_in,
                              void* d_out, int out_size) {
    const float* X = (const float*)d_in[0];
    const float* C = (const float*)d_in[1];
    float* out = (float*)d_out;
    float* o_qh    = out;
    float* o_qs    = out + (size_t)NB * ND;
    float* o_idx   = out + 2ULL * NB * ND;
    float* o_probs = o_idx + NB;
    float* o_loss  = o_probs + NM;

    cudaFuncSetAttribute(mma_gemm_kernel, cudaFuncAttributeMaxDynamicSharedMemorySize,
                         4 * STAGE_BYTES);

    reset_kernel<<<1, 32>>>();
    norms_kernel<<<dim3(NB, 2), 128>>>(X, C);
    split_kernel<<<16384, 256>>>(X, C);
    mma_gemm_kernel<<<dim3(64, 64), 256, 4 * STAGE_BYTES>>>();
    finalize_kernel<<<1, 1>>>();
    transpose_kernel<<<dim3(128, 128), 256>>>();
    reduceS_kernel<<<1, 1024>>>();
    init_rc_kernel<<<32, 256>>>();
    for (int it = 0; it < 50; it++) {
        pass_kernel<<<1024, 256>>>(0);
        pass_kernel<<<1024, 256>>>(1);
    }
    probs_kernel<<<1024, 256>>>(o_probs, o_idx);
    epilogue_kernel<<<NB, 128>>>(X, C, o_qh, o_qs, o_loss);
}

// round 12
// speedup vs baseline: 1.0121x; 1.0118x over previous
#include <cuda_runtime.h>
#include <cuda_bf16.h>
#include <cstdint>

#define NB 8192
#define NK 8192
#define ND 512
#define NM (8192ULL * 8192ULL)
#define GK 1536

// ---------------- static device scratch ----------------
__device__ float  g_Dm[NM];          // d2, row-major (256 MB)
__device__ float  g_DmT[NM];         // d2 transposed (256 MB)
__device__ __nv_bfloat16 g_Xe[8192ULL * GK];  // [x1|x1|x2]
__device__ __nv_bfloat16 g_Ce[8192ULL * GK];  // [c1|c2|c1]
__device__ float  g_nx[NB];
__device__ float  g_nc[NK];
__device__ double g_r[NB];
__device__ double g_c[NK];
__device__ float  g_zr[NB];          // log2(r) + k2
__device__ float  g_zc[NK];          // log2(c) + k2
__device__ double g_Spart[16384];
__device__ double g_S;
__device__ unsigned g_maxbits;
__device__ unsigned g_minbits;
__device__ float  g_k1;
__device__ float  g_k2;
__device__ int    g_idx[NB];

__device__ __forceinline__ unsigned encf(float f) {
    unsigned u = __float_as_uint(f);
    return (u & 0x80000000u) ? ~u : (u | 0x80000000u);
}
__device__ __forceinline__ float decf(unsigned u) {
    return (u & 0x80000000u) ? __uint_as_float(u & 0x7FFFFFFFu) : __uint_as_float(~u);
}
__device__ __forceinline__ float log2_of_double(double v) {
    int e; double m = frexp(v, &e);
    return (float)e + log2f((float)m);
}
__device__ __forceinline__ uint32_t smem_u32(const void* p) {
    uint32_t a;
    asm("{ .reg .u64 t; cvta.to.shared.u64 t, %1; cvt.u32.u64 %0, t; }" : "=r"(a) : "l"(p));
    return a;
}
__device__ __forceinline__ void cpa16(uint32_t s, const void* g) {
    asm volatile("cp.async.cg.shared.global [%0], [%1], 16;" :: "r"(s), "l"(g) : "memory");
}
#define CPA_COMMIT() asm volatile("cp.async.commit_group;" ::: "memory")
template <int N> __device__ __forceinline__ void cpa_wait() {
    asm volatile("cp.async.wait_group %0;" :: "n"(N) : "memory");
}
__device__ __forceinline__ void ldsm4(uint32_t* r, uint32_t addr) {
    asm volatile("ldmatrix.sync.aligned.m8n8.x4.shared.b16 {%0,%1,%2,%3}, [%4];"
        : "=r"(r[0]), "=r"(r[1]), "=r"(r[2]), "=r"(r[3]) : "r"(addr));
}
__device__ __forceinline__ void mma16816(float* d, const uint32_t* a, uint32_t b0, uint32_t b1) {
    asm volatile("mma.sync.aligned.m16n8k16.row.col.f32.bf16.bf16.f32 "
        "{%0,%1,%2,%3}, {%4,%5,%6,%7}, {%8,%9}, {%0,%1,%2,%3};"
        : "+f"(d[0]), "+f"(d[1]), "+f"(d[2]), "+f"(d[3])
        : "r"(a[0]), "r"(a[1]), "r"(a[2]), "r"(a[3]), "r"(b0), "r"(b1));
}

// ---------------- reset ----------------
__global__ void reset_kernel() {
    if (threadIdx.x == 0) { g_maxbits = 0u; g_minbits = 0xFFFFFFFFu; }
}

// ---------------- row norms ----------------
__global__ __launch_bounds__(128) void norms_kernel(const float* __restrict__ X,
                                                    const float* __restrict__ C) {
    int row = blockIdx.x;
    const float* p = (blockIdx.y == 0 ? X : C) + (size_t)row * ND;
    float4 v = ((const float4*)p)[threadIdx.x];
    double s = (double)v.x * v.x + (double)v.y * v.y + (double)v.z * v.z + (double)v.w * v.w;
    for (int o = 16; o; o >>= 1) s += __shfl_down_sync(0xffffffffu, s, o);
    __shared__ double sm[4];
    if ((threadIdx.x & 31) == 0) sm[threadIdx.x >> 5] = s;
    __syncthreads();
    if (threadIdx.x == 0) {
        double t = (sm[0] + sm[1]) + (sm[2] + sm[3]);
        if (blockIdx.y == 0) g_nx[row] = (float)t; else g_nc[row] = (float)t;
    }
}

// ---------------- split-bf16 prep ----------------
__global__ __launch_bounds__(256) void split_kernel(const float* __restrict__ X,
                                                    const float* __restrict__ C) {
    size_t idx = (size_t)blockIdx.x * 256 + threadIdx.x;
    size_t row = idx >> 9, k = idx & 511;
    {
        float x = X[idx];
        __nv_bfloat16 b1 = __float2bfloat16(x);
        __nv_bfloat16 b2 = __float2bfloat16(x - __bfloat162float(b1));
        __nv_bfloat16* d = g_Xe + row * GK + k;
        d[0] = b1; d[512] = b1; d[1024] = b2;
    }
    {
        float c = C[idx];
        __nv_bfloat16 b1 = __float2bfloat16(c);
        __nv_bfloat16 b2 = __float2bfloat16(c - __bfloat162float(b1));
        __nv_bfloat16* d = g_Ce + row * GK + k;
        d[0] = b1; d[512] = b2; d[1024] = b1;
    }
}

// ---------------- HMMA GEMM: 3-stage cp.async, compile-time stage indices, 2 CTA/SM ----------------
#define SPITCH 40                      // bf16 per smem row (80 B)
#define STAGE_BYTES 20480              // A(10240)+B(10240) per stage
#define NCH (GK / 32)                  // 48 chunks (divisible by 3)

__global__ __launch_bounds__(256, 2) void mma_gemm_kernel() {
    extern __shared__ __align__(16) char gsm[];
    const int tid = threadIdx.x;
    const int lane = tid & 31, wid = tid >> 5;
    const int wm = wid & 3, wn = wid >> 2;
    const int bi = blockIdx.y << 7, bj = blockIdx.x << 7;
    const uint32_t sbase = smem_u32(gsm);
    const __nv_bfloat16* Ag = g_Xe + (size_t)bi * GK;
    const __nv_bfloat16* Bg = g_Ce + (size_t)bj * GK;

    float acc[2][8][4];
#pragma unroll
    for (int t = 0; t < 2; t++)
#pragma unroll
        for (int u = 0; u < 8; u++)
#pragma unroll
            for (int v = 0; v < 4; v++) acc[t][u][v] = 0.f;

#define LOAD_CHUNK(c, st)                                                             \
    {                                                                                 \
        _Pragma("unroll")                                                             \
        for (int t = 0; t < 2; t++) {                                                 \
            int s_ = tid + (t << 8);                                                  \
            int r_ = s_ >> 2, sg = (s_ & 3) << 3;                                     \
            uint32_t so = (uint32_t)(st) * STAGE_BYTES + r_ * (SPITCH * 2) + sg * 2;  \
            const size_t go = (size_t)r_ * GK + (size_t)(c) * 32 + sg;                \
            cpa16(sbase + so, Ag + go);                                               \
            cpa16(sbase + so + 10240u, Bg + go);                                      \
        }                                                                             \
    }

    LOAD_CHUNK(0, 0); CPA_COMMIT();
    LOAD_CHUNK(1, 1); CPA_COMMIT();

    const uint32_t aRowOff = (uint32_t)(wm * 32 + (lane & 15)) * (SPITCH * 2);
    const uint32_t aColOff = (uint32_t)((lane >> 4) << 3) * 2;
    const uint32_t bRowBase = (uint32_t)(wn * 64 + (lane & 7) + (((lane >> 4) & 1) << 3));
    const uint32_t bColOff = (uint32_t)(((lane >> 3) & 1) << 3) * 2;

#define STEP(c, s)                                                                    \
    {                                                                                 \
        cpa_wait<1>();                                                                \
        __syncthreads();                                                              \
        if ((c) + 2 < NCH) LOAD_CHUNK((c) + 2, ((s) + 2) % 3);                        \
        CPA_COMMIT();                                                                 \
        const uint32_t abase = sbase + (uint32_t)(s) * STAGE_BYTES;                   \
        const uint32_t bbase = abase + 10240u;                                        \
        _Pragma("unroll")                                                             \
        for (int kk = 0; kk < 2; kk++) {                                              \
            uint32_t a[2][4], b[4][4];                                                \
            _Pragma("unroll")                                                         \
            for (int t = 0; t < 2; t++)                                               \
                ldsm4(a[t], abase + aRowOff + (uint32_t)(t * 16) * (SPITCH * 2)       \
                            + aColOff + (uint32_t)(kk * 16) * 2);                     \
            _Pragma("unroll")                                                         \
            for (int p = 0; p < 4; p++)                                               \
                ldsm4(b[p], bbase + (bRowBase + p * 16) * (SPITCH * 2)                \
                            + bColOff + (uint32_t)(kk * 16) * 2);                     \
            _Pragma("unroll")                                                         \
            for (int t = 0; t < 2; t++)                                               \
                _Pragma("unroll")                                                     \
                for (int u = 0; u < 8; u++)                                           \
                    mma16816(acc[t][u], a[t], b[u >> 1][(u & 1) << 1],                \
                             b[u >> 1][((u & 1) << 1) + 1]);                          \
        }                                                                             \
    }

    for (int ci = 0; ci < NCH; ci += 3) {
        STEP(ci + 0, 0);
        STEP(ci + 1, 1);
        STEP(ci + 2, 2);
    }

    float lmx = -3.4e38f, lmn = 3.4e38f;
#pragma unroll
    for (int t = 0; t < 2; t++) {
        int r0 = bi + wm * 32 + t * 16 + (lane >> 2);
        float nx0 = g_nx[r0], nx1 = g_nx[r0 + 8];
#pragma unroll
        for (int u = 0; u < 8; u++) {
            int col = bj + wn * 64 + u * 8 + ((lane & 3) << 1);
            float nc0 = g_nc[col], nc1 = g_nc[col + 1];
            float d00 = (nx0 + nc0) - 2.0f * acc[t][u][0];
            float d01 = (nx0 + nc1) - 2.0f * acc[t][u][1];
            float d10 = (nx1 + nc0) - 2.0f * acc[t][u][2];
            float d11 = (nx1 + nc1) - 2.0f * acc[t][u][3];
            *(float2*)(g_Dm + (size_t)r0 * NK + col) = make_float2(d00, d01);
            *(float2*)(g_Dm + (size_t)(r0 + 8) * NK + col) = make_float2(d10, d11);
            lmx = fmaxf(lmx, fmaxf(fmaxf(d00, d01), fmaxf(d10, d11)));
            lmn = fminf(lmn, fminf(fminf(d00, d01), fminf(d10, d11)));
        }
    }
    for (int o = 16; o; o >>= 1) {
        lmx = fmaxf(lmx, __shfl_down_sync(0xffffffffu, lmx, o));
        lmn = fminf(lmn, __shfl_down_sync(0xffffffffu, lmn, o));
    }
    __shared__ float smx[8], smn[8];
    if (lane == 0) { smx[wid] = lmx; smn[wid] = lmn; }
    __syncthreads();
    if (tid == 0) {
#pragma unroll
        for (int w = 1; w < 8; w++) { lmx = fmaxf(lmx, smx[w]); lmn = fminf(lmn, smn[w]); }
        atomicMax(&g_maxbits, encf(lmx));
        atomicMin(&g_minbits, encf(lmn));
    }
}

__global__ void finalize_kernel() {
    float mx = decf(g_maxbits), mn = decf(g_minbits);
    float mid = (mx + mn) * 0.5f;
    float range = (mx - mid) + 1e-8f;
    float k1 = -480.89834696298781f / range;
    g_k1 = k1;
    g_k2 = -mid * k1;
}

// ---------------- transpose Dm -> DmT + S partials ----------------
__global__ __launch_bounds__(256) void transpose_kernel() {
    __shared__ float tile[64][65];
    __shared__ float sred[16];
    __shared__ float smb;
    const float k1 = g_k1, k2 = g_k2;
    const int tid = threadIdx.x;
    const int lane = tid & 31, warp = tid >> 5;
    const size_t i0 = (size_t)blockIdx.y * 64;
    const size_t j0 = (size_t)blockIdx.x * 64;
    const int r0 = tid >> 4;
    const int c4 = (tid & 15) << 2;

    float va[16];
    float mx = -3.4e38f;
#pragma unroll
    for (int k = 0; k < 4; k++) {
        int r = r0 + (k << 4);
        float4 d = *(const float4*)(g_Dm + (i0 + r) * NK + j0 + c4);
        tile[r][c4 + 0] = d.x; tile[r][c4 + 1] = d.y;
        tile[r][c4 + 2] = d.z; tile[r][c4 + 3] = d.w;
        float z0 = fmaf(d.x, k1, k2), z1 = fmaf(d.y, k1, k2);
        float z2 = fmaf(d.z, k1, k2), z3 = fmaf(d.w, k1, k2);
        va[k * 4 + 0] = z0; va[k * 4 + 1] = z1; va[k * 4 + 2] = z2; va[k * 4 + 3] = z3;
        mx = fmaxf(mx, fmaxf(fmaxf(z0, z1), fmaxf(z2, z3)));
    }
    for (int o = 16; o; o >>= 1) mx = fmaxf(mx, __shfl_down_sync(0xffffffffu, mx, o));
    if (lane == 0) sred[warp] = mx;
    __syncthreads();
    if (tid == 0) {
        float m = sred[0];
#pragma unroll
        for (int w = 1; w < 8; w++) m = fmaxf(m, sred[w]);
        smb = floorf(m);
    }
    __syncthreads();
    const float mbf = smb;
    float s = 0.f;
#pragma unroll
    for (int k = 0; k < 16; k++) s += exp2f(va[k] - mbf);
    for (int o = 16; o; o >>= 1) s += __shfl_down_sync(0xffffffffu, s, o);
    if (lane == 0) sred[8 + warp] = s;
    __syncthreads();
    if (tid == 0) {
        float tot = 0.f;
#pragma unroll
        for (int w = 0; w < 8; w++) tot += sred[8 + w];
        g_Spart[blockIdx.y * 128 + blockIdx.x] = ldexp((double)tot, (int)mbf);
    }
#pragma unroll
    for (int k = 0; k < 4; k++) {
        int r = r0 + (k << 4);
        float4 v = make_float4(tile[c4 + 0][r], tile[c4 + 1][r], tile[c4 + 2][r], tile[c4 + 3][r]);
        *(float4*)(g_DmT + (j0 + r) * NK + i0 + c4) = v;
    }
}

__global__ __launch_bounds__(1024) void reduceS_kernel() {
    int tid = threadIdx.x;
    double s = 0.0;
#pragma unroll
    for (int k = 0; k < 16; k++) s += g_Spart[tid + k * 1024];
    __shared__ double sm[1024];
    sm[tid] = s;
    __syncthreads();
    for (int o = 512; o; o >>= 1) {
        if (tid < o) sm[tid] += sm[tid + o];
        __syncthreads();
    }
    if (tid == 0) g_S = sm[0];
}

__global__ void init_rc_kernel() {
    int t = blockIdx.x * blockDim.x + threadIdx.x;
    double S = g_S;
    float k2 = g_k2;
    if (t < NB) { g_r[t] = 1.0 / S; g_zr[t] = k2 - log2_of_double(S); }
    if (t < NK) { g_c[t] = 1.0;     g_zc[t] = k2; }
}

// ---------------- Sinkhorn pass: warp-per-row over Dm/DmT with affine ----------------
__global__ __launch_bounds__(256) void pass_kernel(int dir) {
    const float* __restrict__ ZA   = dir ? g_DmT : g_Dm;
    const float* __restrict__ zo   = dir ? g_zr  : g_zc;
    double* __restrict__      vec  = dir ? g_c   : g_r;
    float* __restrict__       zvec = dir ? g_zc  : g_zr;
    const float k1 = g_k1, k2 = g_k2;

    const int lane = threadIdx.x & 31;
    const int i = (blockIdx.x << 3) + (threadIdx.x >> 5);
    const float4* a4 = (const float4*)(ZA + (size_t)i * NK);
    const float4* c4 = (const float4*)zo;

    float M = 0.f, E = -3.4e38f;
#pragma unroll 1
    for (int ch = 0; ch < 8; ch++) {
        float t[32];
        float cmx = -3.4e38f;
#pragma unroll
        for (int v = 0; v < 8; v++) {
            int j4 = (ch << 8) + (v << 5) + lane;
            float4 a = a4[j4];
            float4 c = __ldg(&c4[j4]);
            float t0 = fmaf(a.x, k1, c.x), t1 = fmaf(a.y, k1, c.y);
            float t2 = fmaf(a.z, k1, c.z), t3 = fmaf(a.w, k1, c.w);
            t[v * 4 + 0] = t0; t[v * 4 + 1] = t1; t[v * 4 + 2] = t2; t[v * 4 + 3] = t3;
            cmx = fmaxf(cmx, fmaxf(fmaxf(t0, t1), fmaxf(t2, t3)));
        }
        float s0 = 0.f, s1 = 0.f, s2 = 0.f, s3 = 0.f;
#pragma unroll
        for (int v = 0; v < 8; v++) {
            s0 += exp2f(t[v * 4 + 0] - cmx);
            s1 += exp2f(t[v * 4 + 1] - cmx);
            s2 += exp2f(t[v * 4 + 2] - cmx);
            s3 += exp2f(t[v * 4 + 3] - cmx);
        }
        float s = (s0 + s1) + (s2 + s3);
        if (cmx > E) { M = M * exp2f(E - cmx) + s; E = cmx; }
        else         { M += s * exp2f(cmx - E); }
    }
    for (int o = 16; o; o >>= 1) {
        float oe = __shfl_down_sync(0xffffffffu, E, o);
        float om = __shfl_down_sync(0xffffffffu, M, o);
        if (oe > E) { M = M * exp2f(E - oe) + om; E = oe; }
        else        { M += om * exp2f(oe - E); }
    }
    if (lane == 0) {
        float Ei = floorf(E);
        double y = ldexp((double)(M * exp2f(E - Ei)), (int)Ei);
        double v = vec[i];
        double vn = v / ((v * y) + 1e-8) / 8192.0;
        vec[i] = vn;
        zvec[i] = k2 + log2_of_double(vn);
    }
}

// ---------------- probs + argmax: warp-per-row ----------------
__global__ __launch_bounds__(256) void probs_kernel(float* __restrict__ out_probs,
                                                    float* __restrict__ out_idx) {
    const int lane = threadIdx.x & 31;
    const int i = (blockIdx.x << 3) + (threadIdx.x >> 5);
    const float k1 = g_k1;
    const float lR = log2_of_double(8192.0 * g_r[i]);
    const float4* a4 = (const float4*)(g_Dm + (size_t)i * NK);
    const float4* c4 = (const float4*)g_zc;
    float4* o4 = (float4*)(out_probs + (size_t)i * NK);

    float best = -3.4e38f; int bj = 0x7FFFFFFF;
#pragma unroll 4
    for (int v = 0; v < 64; v++) {
        int j4 = (v << 5) + lane;
        float4 a = a4[j4];
        float4 c = __ldg(&c4[j4]);
        float t0 = fmaf(a.x, k1, c.x), t1 = fmaf(a.y, k1, c.y);
        float t2 = fmaf(a.z, k1, c.z), t3 = fmaf(a.w, k1, c.w);
        o4[j4] = make_float4(exp2f(t0 + lR), exp2f(t1 + lR), exp2f(t2 + lR), exp2f(t3 + lR));
        int jb = j4 << 2;
        if (t0 > best) { best = t0; bj = jb; }
        if (t1 > best) { best = t1; bj = jb + 1; }
        if (t2 > best) { best = t2; bj = jb + 2; }
        if (t3 > best) { best = t3; bj = jb + 3; }
    }
    for (int o = 16; o; o >>= 1) {
        float ov = __shfl_down_sync(0xffffffffu, best, o);
        int oi = __shfl_down_sync(0xffffffffu, bj, o);
        if (ov > best || (ov == best && oi < bj)) { best = ov; bj = oi; }
    }
    if (lane == 0) { g_idx[i] = bj; out_idx[i] = (float)bj; }
}

// ---------------- epilogue ----------------
__global__ __launch_bounds__(128) void epilogue_kernel(const float* __restrict__ X,
                                                       const float* __restrict__ C,
                                                       float* __restrict__ qh,
                                                       float* __restrict__ qs,
                                                       float* __restrict__ loss) {
    int i = blockIdx.x;
    int idx = g_idx[i];
    const float4* cb = (const float4*)(C + (size_t)idx * ND);
    const float4* xr = (const float4*)(X + (size_t)i * ND);
    float4* oh = (float4*)(qh + (size_t)i * ND);
    float4* os = (float4*)(qs + (size_t)i * ND);
    int t = threadIdx.x;
    float4 c4 = cb[t];
    float4 x4 = xr[t];
    oh[t] = c4;
    float dx = c4.x - x4.x, dy = c4.y - x4.y, dz = c4.z - x4.z, dw = c4.w - x4.w;
    os[t] = make_float4(dx + x4.x, dy + x4.y, dz + x4.z, dw + x4.w);
    double s = (double)dx * dx + (double)dy * dy + (double)dz * dz + (double)dw * dw;
    for (int o = 16; o; o >>= 1) s += __shfl_down_sync(0xffffffffu, s, o);
    __shared__ double sm[4];
    if ((t & 31) == 0) sm[t >> 5] = s;
    __syncthreads();
    if (t == 0) {
        double tot = (sm[0] + sm[1]) + (sm[2] + sm[3]);
        float cl = (float)(tot / (double)ND);
        loss[i] = cl + 0.25f * cl;
    }
}

// ---------------- launch ----------------
extern "C" void kernel_launch(void* const* d_in, const int* in_sizes, int n_in,
                              void* d_out, int out_size) {
    const float* X = (const float*)d_in[0];
    const float* C = (const float*)d_in[1];
    float* out = (float*)d_out;
    float* o_qh    = out;
    float* o_qs    = out + (size_t)NB * ND;
    float* o_idx   = out + 2ULL * NB * ND;
    float* o_probs = o_idx + NB;
    float* o_loss  = o_probs + NM;

    cudaFuncSetAttribute(mma_gemm_kernel, cudaFuncAttributeMaxDynamicSharedMemorySize,
                         3 * STAGE_BYTES);

    reset_kernel<<<1, 32>>>();
    norms_kernel<<<dim3(NB, 2), 128>>>(X, C);
    split_kernel<<<16384, 256>>>(X, C);
    mma_gemm_kernel<<<dim3(64, 64), 256, 3 * STAGE_BYTES>>>();
    finalize_kernel<<<1, 1>>>();
    transpose_kernel<<<dim3(128, 128), 256>>>();
    reduceS_kernel<<<1, 1024>>>();
    init_rc_kernel<<<32, 256>>>();
    for (int it = 0; it < 50; it++) {
        pass_kernel<<<1024, 256>>>(0);
        pass_kernel<<<1024, 256>>>(1);
    }
    probs_kernel<<<1024, 256>>>(o_probs, o_idx);
    epilogue_kernel<<<NB, 128>>>(X, C, o_qh, o_qs, o_loss);
}

// round 13
// speedup vs baseline: 1.0247x; 1.0124x over previous
#include <cuda_runtime.h>
#include <cuda_bf16.h>
#include <cstdint>

#define NB 8192
#define NK 8192
#define ND 512
#define NM (8192ULL * 8192ULL)
#define GK 1536

// ---------------- static device scratch ----------------
__device__ float  g_Dm[NM];          // d2, row-major (256 MB)
__device__ float  g_DmT[NM];         // d2 transposed (256 MB)
__device__ __nv_bfloat16 g_Xe[8192ULL * GK];  // [x1|x1|x2]
__device__ __nv_bfloat16 g_Ce[8192ULL * GK];  // [c1|c2|c1]
__device__ float  g_nx[NB];
__device__ float  g_nc[NK];
__device__ double g_r[NB];
__device__ double g_c[NK];
__device__ float  g_zr[NB];          // log2(r) + k2
__device__ float  g_zc[NK];          // log2(c) + k2
__device__ double g_Spart[16384];
__device__ double g_S;
__device__ unsigned g_maxbits;
__device__ unsigned g_minbits;
__device__ float  g_k1;
__device__ float  g_k2;
__device__ int    g_idx[NB];

__device__ __forceinline__ unsigned encf(float f) {
    unsigned u = __float_as_uint(f);
    return (u & 0x80000000u) ? ~u : (u | 0x80000000u);
}
__device__ __forceinline__ float decf(unsigned u) {
    return (u & 0x80000000u) ? __uint_as_float(u & 0x7FFFFFFFu) : __uint_as_float(~u);
}
__device__ __forceinline__ float log2_of_double(double v) {
    int e; double m = frexp(v, &e);
    return (float)e + log2f((float)m);
}
__device__ __forceinline__ uint32_t smem_u32(const void* p) {
    uint32_t a;
    asm("{ .reg .u64 t; cvta.to.shared.u64 t, %1; cvt.u32.u64 %0, t; }" : "=r"(a) : "l"(p));
    return a;
}
__device__ __forceinline__ void cpa16(uint32_t s, const void* g) {
    asm volatile("cp.async.cg.shared.global [%0], [%1], 16;" :: "r"(s), "l"(g) : "memory");
}
#define CPA_COMMIT() asm volatile("cp.async.commit_group;" ::: "memory")
template <int N> __device__ __forceinline__ void cpa_wait() {
    asm volatile("cp.async.wait_group %0;" :: "n"(N) : "memory");
}
__device__ __forceinline__ void ldsm4(uint32_t* r, uint32_t addr) {
    asm volatile("ldmatrix.sync.aligned.m8n8.x4.shared.b16 {%0,%1,%2,%3}, [%4];"
        : "=r"(r[0]), "=r"(r[1]), "=r"(r[2]), "=r"(r[3]) : "r"(addr));
}
__device__ __forceinline__ void mma16816(float* d, const uint32_t* a, uint32_t b0, uint32_t b1) {
    asm volatile("mma.sync.aligned.m16n8k16.row.col.f32.bf16.bf16.f32 "
        "{%0,%1,%2,%3}, {%4,%5,%6,%7}, {%8,%9}, {%0,%1,%2,%3};"
        : "+f"(d[0]), "+f"(d[1]), "+f"(d[2]), "+f"(d[3])
        : "r"(a[0]), "r"(a[1]), "r"(a[2]), "r"(a[3]), "r"(b0), "r"(b1));
}

// ---------------- reset ----------------
__global__ void reset_kernel() {
    if (threadIdx.x == 0) { g_maxbits = 0u; g_minbits = 0xFFFFFFFFu; }
}

// ---------------- row norms ----------------
__global__ __launch_bounds__(128) void norms_kernel(const float* __restrict__ X,
                                                    const float* __restrict__ C) {
    int row = blockIdx.x;
    const float* p = (blockIdx.y == 0 ? X : C) + (size_t)row * ND;
    float4 v = ((const float4*)p)[threadIdx.x];
    double s = (double)v.x * v.x + (double)v.y * v.y + (double)v.z * v.z + (double)v.w * v.w;
    for (int o = 16; o; o >>= 1) s += __shfl_down_sync(0xffffffffu, s, o);
    __shared__ double sm[4];
    if ((threadIdx.x & 31) == 0) sm[threadIdx.x >> 5] = s;
    __syncthreads();
    if (threadIdx.x == 0) {
        double t = (sm[0] + sm[1]) + (sm[2] + sm[3]);
        if (blockIdx.y == 0) g_nx[row] = (float)t; else g_nc[row] = (float)t;
    }
}

// ---------------- split-bf16 prep ----------------
__global__ __launch_bounds__(256) void split_kernel(const float* __restrict__ X,
                                                    const float* __restrict__ C) {
    size_t idx = (size_t)blockIdx.x * 256 + threadIdx.x;
    size_t row = idx >> 9, k = idx & 511;
    {
        float x = X[idx];
        __nv_bfloat16 b1 = __float2bfloat16(x);
        __nv_bfloat16 b2 = __float2bfloat16(x - __bfloat162float(b1));
        __nv_bfloat16* d = g_Xe + row * GK + k;
        d[0] = b1; d[512] = b1; d[1024] = b2;
    }
    {
        float c = C[idx];
        __nv_bfloat16 b1 = __float2bfloat16(c);
        __nv_bfloat16 b2 = __float2bfloat16(c - __bfloat162float(b1));
        __nv_bfloat16* d = g_Ce + row * GK + k;
        d[0] = b1; d[512] = b2; d[1024] = b1;
    }
}

// ---------------- HMMA GEMM: 3-stage cp.async, compile-time stage indices, 2 CTA/SM ----------------
#define SPITCH 40
#define STAGE_BYTES 20480
#define NCH (GK / 32)

__global__ __launch_bounds__(256, 2) void mma_gemm_kernel() {
    extern __shared__ __align__(16) char gsm[];
    const int tid = threadIdx.x;
    const int lane = tid & 31, wid = tid >> 5;
    const int wm = wid & 3, wn = wid >> 2;
    const int bi = blockIdx.y << 7, bj = blockIdx.x << 7;
    const uint32_t sbase = smem_u32(gsm);
    const __nv_bfloat16* Ag = g_Xe + (size_t)bi * GK;
    const __nv_bfloat16* Bg = g_Ce + (size_t)bj * GK;

    float acc[2][8][4];
#pragma unroll
    for (int t = 0; t < 2; t++)
#pragma unroll
        for (int u = 0; u < 8; u++)
#pragma unroll
            for (int v = 0; v < 4; v++) acc[t][u][v] = 0.f;

#define LOAD_CHUNK(c, st)                                                             \
    {                                                                                 \
        _Pragma("unroll")                                                             \
        for (int t = 0; t < 2; t++) {                                                 \
            int s_ = tid + (t << 8);                                                  \
            int r_ = s_ >> 2, sg = (s_ & 3) << 3;                                     \
            uint32_t so = (uint32_t)(st) * STAGE_BYTES + r_ * (SPITCH * 2) + sg * 2;  \
            const size_t go = (size_t)r_ * GK + (size_t)(c) * 32 + sg;                \
            cpa16(sbase + so, Ag + go);                                               \
            cpa16(sbase + so + 10240u, Bg + go);                                      \
        }                                                                             \
    }

    LOAD_CHUNK(0, 0); CPA_COMMIT();
    LOAD_CHUNK(1, 1); CPA_COMMIT();

    const uint32_t aRowOff = (uint32_t)(wm * 32 + (lane & 15)) * (SPITCH * 2);
    const uint32_t aColOff = (uint32_t)((lane >> 4) << 3) * 2;
    const uint32_t bRowBase = (uint32_t)(wn * 64 + (lane & 7) + (((lane >> 4) & 1) << 3));
    const uint32_t bColOff = (uint32_t)(((lane >> 3) & 1) << 3) * 2;

#define STEP(c, s)                                                                    \
    {                                                                                 \
        cpa_wait<1>();                                                                \
        __syncthreads();                                                              \
        if ((c) + 2 < NCH) LOAD_CHUNK((c) + 2, ((s) + 2) % 3);                        \
        CPA_COMMIT();                                                                 \
        const uint32_t abase = sbase + (uint32_t)(s) * STAGE_BYTES;                   \
        const uint32_t bbase = abase + 10240u;                                        \
        _Pragma("unroll")                                                             \
        for (int kk = 0; kk < 2; kk++) {                                              \
            uint32_t a[2][4], b[4][4];                                                \
            _Pragma("unroll")                                                         \
            for (int t = 0; t < 2; t++)                                               \
                ldsm4(a[t], abase + aRowOff + (uint32_t)(t * 16) * (SPITCH * 2)       \
                            + aColOff + (uint32_t)(kk * 16) * 2);                     \
            _Pragma("unroll")                                                         \
            for (int p = 0; p < 4; p++)                                               \
                ldsm4(b[p], bbase + (bRowBase + p * 16) * (SPITCH * 2)                \
                            + bColOff + (uint32_t)(kk * 16) * 2);                     \
            _Pragma("unroll")                                                         \
            for (int t = 0; t < 2; t++)                                               \
                _Pragma("unroll")                                                     \
                for (int u = 0; u < 8; u++)                                           \
                    mma16816(acc[t][u], a[t], b[u >> 1][(u & 1) << 1],                \
                             b[u >> 1][((u & 1) << 1) + 1]);                          \
        }                                                                             \
    }

    for (int ci = 0; ci < NCH; ci += 3) {
        STEP(ci + 0, 0);
        STEP(ci + 1, 1);
        STEP(ci + 2, 2);
    }

    float lmx = -3.4e38f, lmn = 3.4e38f;
#pragma unroll
    for (int t = 0; t < 2; t++) {
        int r0 = bi + wm * 32 + t * 16 + (lane >> 2);
        float nx0 = g_nx[r0], nx1 = g_nx[r0 + 8];
#pragma unroll
        for (int u = 0; u < 8; u++) {
            int col = bj + wn * 64 + u * 8 + ((lane & 3) << 1);
            float nc0 = g_nc[col], nc1 = g_nc[col + 1];
            float d00 = (nx0 + nc0) - 2.0f * acc[t][u][0];
            float d01 = (nx0 + nc1) - 2.0f * acc[t][u][1];
            float d10 = (nx1 + nc0) - 2.0f * acc[t][u][2];
            float d11 = (nx1 + nc1) - 2.0f * acc[t][u][3];
            *(float2*)(g_Dm + (size_t)r0 * NK + col) = make_float2(d00, d01);
            *(float2*)(g_Dm + (size_t)(r0 + 8) * NK + col) = make_float2(d10, d11);
            lmx = fmaxf(lmx, fmaxf(fmaxf(d00, d01), fmaxf(d10, d11)));
            lmn = fminf(lmn, fminf(fminf(d00, d01), fminf(d10, d11)));
        }
    }
    for (int o = 16; o; o >>= 1) {
        lmx = fmaxf(lmx, __shfl_down_sync(0xffffffffu, lmx, o));
        lmn = fminf(lmn, __shfl_down_sync(0xffffffffu, lmn, o));
    }
    __shared__ float smx[8], smn[8];
    if (lane == 0) { smx[wid] = lmx; smn[wid] = lmn; }
    __syncthreads();
    if (tid == 0) {
#pragma unroll
        for (int w = 1; w < 8; w++) { lmx = fmaxf(lmx, smx[w]); lmn = fminf(lmn, smn[w]); }
        atomicMax(&g_maxbits, encf(lmx));
        atomicMin(&g_minbits, encf(lmn));
    }
}

__global__ void finalize_kernel() {
    float mx = decf(g_maxbits), mn = decf(g_minbits);
    float mid = (mx + mn) * 0.5f;
    float range = (mx - mid) + 1e-8f;
    float k1 = -480.89834696298781f / range;
    g_k1 = k1;
    g_k2 = -mid * k1;
}

// ---------------- transpose Dm -> DmT + S partials ----------------
__global__ __launch_bounds__(256) void transpose_kernel() {
    __shared__ float tile[64][65];
    __shared__ float sred[16];
    __shared__ float smb;
    const float k1 = g_k1, k2 = g_k2;
    const int tid = threadIdx.x;
    const int lane = tid & 31, warp = tid >> 5;
    const size_t i0 = (size_t)blockIdx.y * 64;
    const size_t j0 = (size_t)blockIdx.x * 64;
    const int r0 = tid >> 4;
    const int c4 = (tid & 15) << 2;

    float va[16];
    float mx = -3.4e38f;
#pragma unroll
    for (int k = 0; k < 4; k++) {
        int r = r0 + (k << 4);
        float4 d = *(const float4*)(g_Dm + (i0 + r) * NK + j0 + c4);
        tile[r][c4 + 0] = d.x; tile[r][c4 + 1] = d.y;
        tile[r][c4 + 2] = d.z; tile[r][c4 + 3] = d.w;
        float z0 = fmaf(d.x, k1, k2), z1 = fmaf(d.y, k1, k2);
        float z2 = fmaf(d.z, k1, k2), z3 = fmaf(d.w, k1, k2);
        va[k * 4 + 0] = z0; va[k * 4 + 1] = z1; va[k * 4 + 2] = z2; va[k * 4 + 3] = z3;
        mx = fmaxf(mx, fmaxf(fmaxf(z0, z1), fmaxf(z2, z3)));
    }
    for (int o = 16; o; o >>= 1) mx = fmaxf(mx, __shfl_down_sync(0xffffffffu, mx, o));
    if (lane == 0) sred[warp] = mx;
    __syncthreads();
    if (tid == 0) {
        float m = sred[0];
#pragma unroll
        for (int w = 1; w < 8; w++) m = fmaxf(m, sred[w]);
        smb = floorf(m);
    }
    __syncthreads();
    const float mbf = smb;
    float s = 0.f;
#pragma unroll
    for (int k = 0; k < 16; k++) s += exp2f(va[k] - mbf);
    for (int o = 16; o; o >>= 1) s += __shfl_down_sync(0xffffffffu, s, o);
    if (lane == 0) sred[8 + warp] = s;
    __syncthreads();
    if (tid == 0) {
        float tot = 0.f;
#pragma unroll
        for (int w = 0; w < 8; w++) tot += sred[8 + w];
        g_Spart[blockIdx.y * 128 + blockIdx.x] = ldexp((double)tot, (int)mbf);
    }
#pragma unroll
    for (int k = 0; k < 4; k++) {
        int r = r0 + (k << 4);
        float4 v = make_float4(tile[c4 + 0][r], tile[c4 + 1][r], tile[c4 + 2][r], tile[c4 + 3][r]);
        *(float4*)(g_DmT + (j0 + r) * NK + i0 + c4) = v;
    }
}

__global__ __launch_bounds__(1024) void reduceS_kernel() {
    int tid = threadIdx.x;
    double s = 0.0;
#pragma unroll
    for (int k = 0; k < 16; k++) s += g_Spart[tid + k * 1024];
    __shared__ double sm[1024];
    sm[tid] = s;
    __syncthreads();
    for (int o = 512; o; o >>= 1) {
        if (tid < o) sm[tid] += sm[tid + o];
        __syncthreads();
    }
    if (tid == 0) g_S = sm[0];
}

__global__ void init_rc_kernel() {
    int t = blockIdx.x * blockDim.x + threadIdx.x;
    double S = g_S;
    float k2 = g_k2;
    if (t < NB) { g_r[t] = 1.0 / S; g_zr[t] = k2 - log2_of_double(S); }
    if (t < NK) { g_c[t] = 1.0;     g_zc[t] = k2; }
}

// ---------------- Sinkhorn pass: 2 warps per row (half-row each), smem merge ----------------
__global__ __launch_bounds__(256) void pass_kernel(int dir) {
    const float* __restrict__ ZA   = dir ? g_DmT : g_Dm;
    const float* __restrict__ zo   = dir ? g_zr  : g_zc;
    double* __restrict__      vec  = dir ? g_c   : g_r;
    float* __restrict__       zvec = dir ? g_zc  : g_zr;
    const float k1 = g_k1, k2 = g_k2;

    __shared__ float sM[8], sE[8];
    const int tid = threadIdx.x;
    const int lane = tid & 31;
    const int wid = tid >> 5;             // 0..7
    const int rloc = wid >> 1;            // 0..3
    const int half = wid & 1;             // 0/1
    const int i = (blockIdx.x << 2) + rloc;
    const float4* a4 = (const float4*)(ZA + (size_t)i * NK);
    const float4* c4 = (const float4*)zo;
    const int base = half << 10;          // float4 offset: 0 or 1024

    float M = 0.f, E = -3.4e38f;
#pragma unroll 1
    for (int ch = 0; ch < 4; ch++) {
        float t[32];
        float cmx = -3.4e38f;
#pragma unroll
        for (int v = 0; v < 8; v++) {
            int j4 = base + (ch << 8) + (v << 5) + lane;
            float4 a = a4[j4];
            float4 c = __ldg(&c4[j4]);
            float t0 = fmaf(a.x, k1, c.x), t1 = fmaf(a.y, k1, c.y);
            float t2 = fmaf(a.z, k1, c.z), t3 = fmaf(a.w, k1, c.w);
            t[v * 4 + 0] = t0; t[v * 4 + 1] = t1; t[v * 4 + 2] = t2; t[v * 4 + 3] = t3;
            cmx = fmaxf(cmx, fmaxf(fmaxf(t0, t1), fmaxf(t2, t3)));
        }
        float s0 = 0.f, s1 = 0.f, s2 = 0.f, s3 = 0.f;
#pragma unroll
        for (int v = 0; v < 8; v++) {
            s0 += exp2f(t[v * 4 + 0] - cmx);
            s1 += exp2f(t[v * 4 + 1] - cmx);
            s2 += exp2f(t[v * 4 + 2] - cmx);
            s3 += exp2f(t[v * 4 + 3] - cmx);
        }
        float s = (s0 + s1) + (s2 + s3);
        if (cmx > E) { M = M * exp2f(E - cmx) + s; E = cmx; }
        else         { M += s * exp2f(cmx - E); }
    }
    for (int o = 16; o; o >>= 1) {
        float oe = __shfl_down_sync(0xffffffffu, E, o);
        float om = __shfl_down_sync(0xffffffffu, M, o);
        if (oe > E) { M = M * exp2f(E - oe) + om; E = oe; }
        else        { M += om * exp2f(oe - E); }
    }
    if (lane == 0) { sM[wid] = M; sE[wid] = E; }
    __syncthreads();
    if (half == 0 && lane == 0) {
        float oM = sM[wid + 1], oE = sE[wid + 1];
        if (oE > E) { M = M * exp2f(E - oE) + oM; E = oE; }
        else        { M += oM * exp2f(oE - E); }
        float Ei = floorf(E);
        double y = ldexp((double)(M * exp2f(E - Ei)), (int)Ei);
        double v = vec[i];
        double vn = v / ((v * y) + 1e-8) / 8192.0;
        vec[i] = vn;
        zvec[i] = k2 + log2_of_double(vn);
    }
}

// ---------------- probs + argmax: 2 warps per row ----------------
__global__ __launch_bounds__(256) void probs_kernel(float* __restrict__ out_probs,
                                                    float* __restrict__ out_idx) {
    __shared__ float sB[8];
    __shared__ int sJ[8];
    const int tid = threadIdx.x;
    const int lane = tid & 31;
    const int wid = tid >> 5;
    const int rloc = wid >> 1;
    const int half = wid & 1;
    const int i = (blockIdx.x << 2) + rloc;
    const float k1 = g_k1;
    const float lR = log2_of_double(8192.0 * g_r[i]);
    const float4* a4 = (const float4*)(g_Dm + (size_t)i * NK);
    const float4* c4 = (const float4*)g_zc;
    float4* o4 = (float4*)(out_probs + (size_t)i * NK);
    const int base = half << 10;

    float best = -3.4e38f; int bj = 0x7FFFFFFF;
#pragma unroll 4
    for (int v = 0; v < 32; v++) {
        int j4 = base + (v << 5) + lane;
        float4 a = a4[j4];
        float4 c = __ldg(&c4[j4]);
        float t0 = fmaf(a.x, k1, c.x), t1 = fmaf(a.y, k1, c.y);
        float t2 = fmaf(a.z, k1, c.z), t3 = fmaf(a.w, k1, c.w);
        o4[j4] = make_float4(exp2f(t0 + lR), exp2f(t1 + lR), exp2f(t2 + lR), exp2f(t3 + lR));
        int jb = j4 << 2;
        if (t0 > best) { best = t0; bj = jb; }
        if (t1 > best) { best = t1; bj = jb + 1; }
        if (t2 > best) { best = t2; bj = jb + 2; }
        if (t3 > best) { best = t3; bj = jb + 3; }
    }
    for (int o = 16; o; o >>= 1) {
        float ov = __shfl_down_sync(0xffffffffu, best, o);
        int oi = __shfl_down_sync(0xffffffffu, bj, o);
        if (ov > best || (ov == best && oi < bj)) { best = ov; bj = oi; }
    }
    if (lane == 0) { sB[wid] = best; sJ[wid] = bj; }
    __syncthreads();
    if (half == 0 && lane == 0) {
        float ov = sB[wid + 1]; int oi = sJ[wid + 1];
        if (ov > best || (ov == best && oi < bj)) { best = ov; bj = oi; }
        g_idx[i] = bj;
        out_idx[i] = (float)bj;
    }
}

// ---------------- epilogue ----------------
__global__ __launch_bounds__(128) void epilogue_kernel(const float* __restrict__ X,
                                                       const float* __restrict__ C,
                                                       float* __restrict__ qh,
                                                       float* __restrict__ qs,
                                                       float* __restrict__ loss) {
    int i = blockIdx.x;
    int idx = g_idx[i];
    const float4* cb = (const float4*)(C + (size_t)idx * ND);
    const float4* xr = (const float4*)(X + (size_t)i * ND);
    float4* oh = (float4*)(qh + (size_t)i * ND);
    float4* os = (float4*)(qs + (size_t)i * ND);
    int t = threadIdx.x;
    float4 c4 = cb[t];
    float4 x4 = xr[t];
    oh[t] = c4;
    float dx = c4.x - x4.x, dy = c4.y - x4.y, dz = c4.z - x4.z, dw = c4.w - x4.w;
    os[t] = make_float4(dx + x4.x, dy + x4.y, dz + x4.z, dw + x4.w);
    double s = (double)dx * dx + (double)dy * dy + (double)dz * dz + (double)dw * dw;
    for (int o = 16; o; o >>= 1) s += __shfl_down_sync(0xffffffffu, s, o);
    __shared__ double sm[4];
    if ((t & 31) == 0) sm[t >> 5] = s;
    __syncthreads();
    if (t == 0) {
        double tot = (sm[0] + sm[1]) + (sm[2] + sm[3]);
        float cl = (float)(tot / (double)ND);
        loss[i] = cl + 0.25f * cl;
    }
}

// ---------------- launch ----------------
extern "C" void kernel_launch(void* const* d_in, const int* in_sizes, int n_in,
                              void* d_out, int out_size) {
    const float* X = (const float*)d_in[0];
    const float* C = (const float*)d_in[1];
    float* out = (float*)d_out;
    float* o_qh    = out;
    float* o_qs    = out + (size_t)NB * ND;
    float* o_idx   = out + 2ULL * NB * ND;
    float* o_probs = o_idx + NB;
    float* o_loss  = o_probs + NM;

    cudaFuncSetAttribute(mma_gemm_kernel, cudaFuncAttributeMaxDynamicSharedMemorySize,
                         3 * STAGE_BYTES);

    reset_kernel<<<1, 32>>>();
    norms_kernel<<<dim3(NB, 2), 128>>>(X, C);
    split_kernel<<<16384, 256>>>(X, C);
    mma_gemm_kernel<<<dim3(64, 64), 256, 3 * STAGE_BYTES>>>();
    finalize_kernel<<<1, 1>>>();
    transpose_kernel<<<dim3(128, 128), 256>>>();
    reduceS_kernel<<<1, 1024>>>();
    init_rc_kernel<<<32, 256>>>();
    for (int it = 0; it < 50; it++) {
        pass_kernel<<<2048, 256>>>(0);
        pass_kernel<<<2048, 256>>>(1);
    }
    probs_kernel<<<2048, 256>>>(o_probs, o_idx);
    epilogue_kernel<<<NB, 128>>>(X, C, o_qh, o_qs, o_loss);
}

// round 15
// speedup vs baseline: 1.0343x; 1.0093x over previous
#include <cuda_runtime.h>
#include <cuda_bf16.h>
#include <cstdint>

#define NB 8192
#define NK 8192
#define ND 512
#define NM (8192ULL * 8192ULL)
#define GK 1536
#define PERSIST_ROWS 1792   // 56 MB per matrix pinned in L2 (112 MB total < 126 MB)

// ---------------- static device scratch ----------------
__device__ float  g_Dm[NM];          // d2, row-major (256 MB)
__device__ float  g_DmT[NM];         // d2 transposed (256 MB)
__device__ __nv_bfloat16 g_Xe[8192ULL * GK];  // [x1|x1|x2]
__device__ __nv_bfloat16 g_Ce[8192ULL * GK];  // [c1|c2|c1]
__device__ float  g_nx[NB];
__device__ float  g_nc[NK];
__device__ double g_r[NB];
__device__ double g_c[NK];
__device__ float  g_zr[NB];          // log2(r) + k2
__device__ float  g_zc[NK];          // log2(c) + k2
__device__ double g_Spart[16384];
__device__ double g_S;
__device__ unsigned g_maxbits;
__device__ unsigned g_minbits;
__device__ float  g_k1;
__device__ float  g_k2;
__device__ int    g_idx[NB];

__device__ __forceinline__ unsigned encf(float f) {
    unsigned u = __float_as_uint(f);
    return (u & 0x80000000u) ? ~u : (u | 0x80000000u);
}
__device__ __forceinline__ float decf(unsigned u) {
    return (u & 0x80000000u) ? __uint_as_float(u & 0x7FFFFFFFu) : __uint_as_float(~u);
}
__device__ __forceinline__ float log2_of_double(double v) {
    int e; double m = frexp(v, &e);
    return (float)e + log2f((float)m);
}
__device__ __forceinline__ uint32_t smem_u32(const void* p) {
    uint32_t a;
    asm("{ .reg .u64 t; cvta.to.shared.u64 t, %1; cvt.u32.u64 %0, t; }" : "=r"(a) : "l"(p));
    return a;
}
__device__ __forceinline__ void cpa16(uint32_t s, const void* g) {
    asm volatile("cp.async.cg.shared.global [%0], [%1], 16;" :: "r"(s), "l"(g) : "memory");
}
#define CPA_COMMIT() asm volatile("cp.async.commit_group;" ::: "memory")
template <int N> __device__ __forceinline__ void cpa_wait() {
    asm volatile("cp.async.wait_group %0;" :: "n"(N) : "memory");
}
__device__ __forceinline__ void ldsm4(uint32_t* r, uint32_t addr) {
    asm volatile("ldmatrix.sync.aligned.m8n8.x4.shared.b16 {%0,%1,%2,%3}, [%4];"
        : "=r"(r[0]), "=r"(r[1]), "=r"(r[2]), "=r"(r[3]) : "r"(addr));
}
__device__ __forceinline__ void mma16816(float* d, const uint32_t* a, uint32_t b0, uint32_t b1) {
    asm volatile("mma.sync.aligned.m16n8k16.row.col.f32.bf16.bf16.f32 "
        "{%0,%1,%2,%3}, {%4,%5,%6,%7}, {%8,%9}, {%0,%1,%2,%3};"
        : "+f"(d[0]), "+f"(d[1]), "+f"(d[2]), "+f"(d[3])
        : "r"(a[0]), "r"(a[1]), "r"(a[2]), "r"(a[3]), "r"(b0), "r"(b1));
}

// 256-bit L2 eviction-hinted load: 8 floats (32B aligned)
template<bool KEEP>
__device__ __forceinline__ void ld8h(const float* p, float4& lo, float4& hi) {
    uint64_t x0, x1, x2, x3;
    if (KEEP)
        asm("ld.global.nc.L2::evict_last.v4.b64 {%0,%1,%2,%3}, [%4];"
            : "=l"(x0), "=l"(x1), "=l"(x2), "=l"(x3) : "l"(p));
    else
        asm("ld.global.nc.L2::evict_first.v4.b64 {%0,%1,%2,%3}, [%4];"
            : "=l"(x0), "=l"(x1), "=l"(x2), "=l"(x3) : "l"(p));
    lo.x = __uint_as_float((unsigned)x0); lo.y = __uint_as_float((unsigned)(x0 >> 32));
    lo.z = __uint_as_float((unsigned)x1); lo.w = __uint_as_float((unsigned)(x1 >> 32));
    hi.x = __uint_as_float((unsigned)x2); hi.y = __uint_as_float((unsigned)(x2 >> 32));
    hi.z = __uint_as_float((unsigned)x3); hi.w = __uint_as_float((unsigned)(x3 >> 32));
}

// ---------------- reset ----------------
__global__ void reset_kernel() {
    if (threadIdx.x == 0) { g_maxbits = 0u; g_minbits = 0xFFFFFFFFu; }
}

// ---------------- row norms ----------------
__global__ __launch_bounds__(128) void norms_kernel(const float* __restrict__ X,
                                                    const float* __restrict__ C) {
    int row = blockIdx.x;
    const float* p = (blockIdx.y == 0 ? X : C) + (size_t)row * ND;
    float4 v = ((const float4*)p)[threadIdx.x];
    double s = (double)v.x * v.x + (double)v.y * v.y + (double)v.z * v.z + (double)v.w * v.w;
    for (int o = 16; o; o >>= 1) s += __shfl_down_sync(0xffffffffu, s, o);
    __shared__ double sm[4];
    if ((threadIdx.x & 31) == 0) sm[threadIdx.x >> 5] = s;
    __syncthreads();
    if (threadIdx.x == 0) {
        double t = (sm[0] + sm[1]) + (sm[2] + sm[3]);
        if (blockIdx.y == 0) g_nx[row] = (float)t; else g_nc[row] = (float)t;
    }
}

// ---------------- split-bf16 prep ----------------
__global__ __launch_bounds__(256) void split_kernel(const float* __restrict__ X,
                                                    const float* __restrict__ C) {
    size_t idx = (size_t)blockIdx.x * 256 + threadIdx.x;
    size_t row = idx >> 9, k = idx & 511;
    {
        float x = X[idx];
        __nv_bfloat16 b1 = __float2bfloat16(x);
        __nv_bfloat16 b2 = __float2bfloat16(x - __bfloat162float(b1));
        __nv_bfloat16* d = g_Xe + row * GK + k;
        d[0] = b1; d[512] = b1; d[1024] = b2;
    }
    {
        float c = C[idx];
        __nv_bfloat16 b1 = __float2bfloat16(c);
        __nv_bfloat16 b2 = __float2bfloat16(c - __bfloat162float(b1));
        __nv_bfloat16* d = g_Ce + row * GK + k;
        d[0] = b1; d[512] = b2; d[1024] = b1;
    }
}

// ---------------- HMMA GEMM: 3-stage cp.async, compile-time stage indices, 2 CTA/SM ----------------
#define SPITCH 40
#define STAGE_BYTES 20480
#define NCH (GK / 32)

__global__ __launch_bounds__(256, 2) void mma_gemm_kernel() {
    extern __shared__ __align__(16) char gsm[];
    const int tid = threadIdx.x;
    const int lane = tid & 31, wid = tid >> 5;
    const int wm = wid & 3, wn = wid >> 2;
    const int bi = blockIdx.y << 7, bj = blockIdx.x << 7;
    const uint32_t sbase = smem_u32(gsm);
    const __nv_bfloat16* Ag = g_Xe + (size_t)bi * GK;
    const __nv_bfloat16* Bg = g_Ce + (size_t)bj * GK;

    float acc[2][8][4];
#pragma unroll
    for (int t = 0; t < 2; t++)
#pragma unroll
        for (int u = 0; u < 8; u++)
#pragma unroll
            for (int v = 0; v < 4; v++) acc[t][u][v] = 0.f;

#define LOAD_CHUNK(c, st)                                                             \
    {                                                                                 \
        _Pragma("unroll")                                                             \
        for (int t = 0; t < 2; t++) {                                                 \
            int s_ = tid + (t << 8);                                                  \
            int r_ = s_ >> 2, sg = (s_ & 3) << 3;                                     \
            uint32_t so = (uint32_t)(st) * STAGE_BYTES + r_ * (SPITCH * 2) + sg * 2;  \
            const size_t go = (size_t)r_ * GK + (size_t)(c) * 32 + sg;                \
            cpa16(sbase + so, Ag + go);                                               \
            cpa16(sbase + so + 10240u, Bg + go);                                      \
        }                                                                             \
    }

    LOAD_CHUNK(0, 0); CPA_COMMIT();
    LOAD_CHUNK(1, 1); CPA_COMMIT();

    const uint32_t aRowOff = (uint32_t)(wm * 32 + (lane & 15)) * (SPITCH * 2);
    const uint32_t aColOff = (uint32_t)((lane >> 4) << 3) * 2;
    const uint32_t bRowBase = (uint32_t)(wn * 64 + (lane & 7) + (((lane >> 4) & 1) << 3));
    const uint32_t bColOff = (uint32_t)(((lane >> 3) & 1) << 3) * 2;

#define STEP(c, s)                                                                    \
    {                                                                                 \
        cpa_wait<1>();                                                                \
        __syncthreads();                                                              \
        if ((c) + 2 < NCH) LOAD_CHUNK((c) + 2, ((s) + 2) % 3);                        \
        CPA_COMMIT();                                                                 \
        const uint32_t abase = sbase + (uint32_t)(s) * STAGE_BYTES;                   \
        const uint32_t bbase = abase + 10240u;                                        \
        _Pragma("unroll")                                                             \
        for (int kk = 0; kk < 2; kk++) {                                              \
            uint32_t a[2][4], b[4][4];                                                \
            _Pragma("unroll")                                                         \
            for (int t = 0; t < 2; t++)                                               \
                ldsm4(a[t], abase + aRowOff + (uint32_t)(t * 16) * (SPITCH * 2)       \
                            + aColOff + (uint32_t)(kk * 16) * 2);                     \
            _Pragma("unroll")                                                         \
            for (int p = 0; p < 4; p++)                                               \
                ldsm4(b[p], bbase + (bRowBase + p * 16) * (SPITCH * 2)                \
                            + bColOff + (uint32_t)(kk * 16) * 2);                     \
            _Pragma("unroll")                                                         \
            for (int t = 0; t < 2; t++)                                               \
                _Pragma("unroll")                                                     \
                for (int u = 0; u < 8; u++)                                           \
                    mma16816(acc[t][u], a[t], b[u >> 1][(u & 1) << 1],                \
                             b[u >> 1][((u & 1) << 1) + 1]);                          \
        }                                                                             \
    }

    for (int ci = 0; ci < NCH; ci += 3) {
        STEP(ci + 0, 0);
        STEP(ci + 1, 1);
        STEP(ci + 2, 2);
    }

    float lmx = -3.4e38f, lmn = 3.4e38f;
#pragma unroll
    for (int t = 0; t < 2; t++) {
        int r0 = bi + wm * 32 + t * 16 + (lane >> 2);
        float nx0 = g_nx[r0], nx1 = g_nx[r0 + 8];
#pragma unroll
        for (int u = 0; u < 8; u++) {
            int col = bj + wn * 64 + u * 8 + ((lane & 3) << 1);
            float nc0 = g_nc[col], nc1 = g_nc[col + 1];
            float d00 = (nx0 + nc0) - 2.0f * acc[t][u][0];
            float d01 = (nx0 + nc1) - 2.0f * acc[t][u][1];
            float d10 = (nx1 + nc0) - 2.0f * acc[t][u][2];
            float d11 = (nx1 + nc1) - 2.0f * acc[t][u][3];
            *(float2*)(g_Dm + (size_t)r0 * NK + col) = make_float2(d00, d01);
            *(float2*)(g_Dm + (size_t)(r0 + 8) * NK + col) = make_float2(d10, d11);
            lmx = fmaxf(lmx, fmaxf(fmaxf(d00, d01), fmaxf(d10, d11)));
            lmn = fminf(lmn, fminf(fminf(d00, d01), fminf(d10, d11)));
        }
    }
    for (int o = 16; o; o >>= 1) {
        lmx = fmaxf(lmx, __shfl_down_sync(0xffffffffu, lmx, o));
        lmn = fminf(lmn, __shfl_down_sync(0xffffffffu, lmn, o));
    }
    __shared__ float smx[8], smn[8];
    if (lane == 0) { smx[wid] = lmx; smn[wid] = lmn; }
    __syncthreads();
    if (tid == 0) {
#pragma unroll
        for (int w = 1; w < 8; w++) { lmx = fmaxf(lmx, smx[w]); lmn = fminf(lmn, smn[w]); }
        atomicMax(&g_maxbits, encf(lmx));
        atomicMin(&g_minbits, encf(lmn));
    }
}

__global__ void finalize_kernel() {
    float mx = decf(g_maxbits), mn = decf(g_minbits);
    float mid = (mx + mn) * 0.5f;
    float range = (mx - mid) + 1e-8f;
    float k1 = -480.89834696298781f / range;
    g_k1 = k1;
    g_k2 = -mid * k1;
}

// ---------------- transpose Dm -> DmT + S partials ----------------
__global__ __launch_bounds__(256) void transpose_kernel() {
    __shared__ float tile[64][65];
    __shared__ float sred[16];
    __shared__ float smb;
    const float k1 = g_k1, k2 = g_k2;
    const int tid = threadIdx.x;
    const int lane = tid & 31, warp = tid >> 5;
    const size_t i0 = (size_t)blockIdx.y * 64;
    const size_t j0 = (size_t)blockIdx.x * 64;
    const int r0 = tid >> 4;
    const int c4 = (tid & 15) << 2;

    float va[16];
    float mx = -3.4e38f;
#pragma unroll
    for (int k = 0; k < 4; k++) {
        int r = r0 + (k << 4);
        float4 d = *(const float4*)(g_Dm + (i0 + r) * NK + j0 + c4);
        tile[r][c4 + 0] = d.x; tile[r][c4 + 1] = d.y;
        tile[r][c4 + 2] = d.z; tile[r][c4 + 3] = d.w;
        float z0 = fmaf(d.x, k1, k2), z1 = fmaf(d.y, k1, k2);
        float z2 = fmaf(d.z, k1, k2), z3 = fmaf(d.w, k1, k2);
        va[k * 4 + 0] = z0; va[k * 4 + 1] = z1; va[k * 4 + 2] = z2; va[k * 4 + 3] = z3;
        mx = fmaxf(mx, fmaxf(fmaxf(z0, z1), fmaxf(z2, z3)));
    }
    for (int o = 16; o; o >>= 1) mx = fmaxf(mx, __shfl_down_sync(0xffffffffu, mx, o));
    if (lane == 0) sred[warp] = mx;
    __syncthreads();
    if (tid == 0) {
        float m = sred[0];
#pragma unroll
        for (int w = 1; w < 8; w++) m = fmaxf(m, sred[w]);
        smb = floorf(m);
    }
    __syncthreads();
    const float mbf = smb;
    float s = 0.f;
#pragma unroll
    for (int k = 0; k < 16; k++) s += exp2f(va[k] - mbf);
    for (int o = 16; o; o >>= 1) s += __shfl_down_sync(0xffffffffu, s, o);
    if (lane == 0) sred[8 + warp] = s;
    __syncthreads();
    if (tid == 0) {
        float tot = 0.f;
#pragma unroll
        for (int w = 0; w < 8; w++) tot += sred[8 + w];
        g_Spart[blockIdx.y * 128 + blockIdx.x] = ldexp((double)tot, (int)mbf);
    }
#pragma unroll
    for (int k = 0; k < 4; k++) {
        int r = r0 + (k << 4);
        float4 v = make_float4(tile[c4 + 0][r], tile[c4 + 1][r], tile[c4 + 2][r], tile[c4 + 3][r]);
        *(float4*)(g_DmT + (j0 + r) * NK + i0 + c4) = v;
    }
}

__global__ __launch_bounds__(1024) void reduceS_kernel() {
    int tid = threadIdx.x;
    double s = 0.0;
#pragma unroll
    for (int k = 0; k < 16; k++) s += g_Spart[tid + k * 1024];
    __shared__ double sm[1024];
    sm[tid] = s;
    __syncthreads();
    for (int o = 512; o; o >>= 1) {
        if (tid < o) sm[tid] += sm[tid + o];
        __syncthreads();
    }
    if (tid == 0) g_S = sm[0];
}

__global__ void init_rc_kernel() {
    int t = blockIdx.x * blockDim.x + threadIdx.x;
    double S = g_S;
    float k2 = g_k2;
    if (t < NB) { g_r[t] = 1.0 / S; g_zr[t] = k2 - log2_of_double(S); }
    if (t < NK) { g_c[t] = 1.0;     g_zc[t] = k2; }
}

// ---------------- Sinkhorn pass: 2 warps per row, 256-bit L2-hinted loads ----------------
template<bool KEEP>
__device__ __forceinline__ void pass_accum(const float* __restrict__ Arow,
                                           const float4* __restrict__ c4,
                                           int base8, int lane, float k1,
                                           float& M, float& E) {
#pragma unroll 1
    for (int ch = 0; ch < 4; ch++) {
        float t[32];
        float cmx = -3.4e38f;
#pragma unroll
        for (int v = 0; v < 4; v++) {
            int j8 = base8 + (ch << 7) + (v << 5) + lane;
            float4 alo, ahi;
            ld8h<KEEP>(Arow + (size_t)j8 * 8, alo, ahi);
            float4 clo = __ldg(&c4[2 * j8]);
            float4 chi = __ldg(&c4[2 * j8 + 1]);
            float t0 = fmaf(alo.x, k1, clo.x), t1 = fmaf(alo.y, k1, clo.y);
            float t2 = fmaf(alo.z, k1, clo.z), t3 = fmaf(alo.w, k1, clo.w);
            float t4 = fmaf(ahi.x, k1, chi.x), t5 = fmaf(ahi.y, k1, chi.y);
            float t6 = fmaf(ahi.z, k1, chi.z), t7 = fmaf(ahi.w, k1, chi.w);
            t[v * 8 + 0] = t0; t[v * 8 + 1] = t1; t[v * 8 + 2] = t2; t[v * 8 + 3] = t3;
            t[v * 8 + 4] = t4; t[v * 8 + 5] = t5; t[v * 8 + 6] = t6; t[v * 8 + 7] = t7;
            cmx = fmaxf(cmx, fmaxf(fmaxf(fmaxf(t0, t1), fmaxf(t2, t3)),
                                   fmaxf(fmaxf(t4, t5), fmaxf(t6, t7))));
        }
        float s0 = 0.f, s1 = 0.f, s2 = 0.f, s3 = 0.f;
#pragma unroll
        for (int v = 0; v < 8; v++) {
            s0 += exp2f(t[v * 4 + 0] - cmx);
            s1 += exp2f(t[v * 4 + 1] - cmx);
            s2 += exp2f(t[v * 4 + 2] - cmx);
            s3 += exp2f(t[v * 4 + 3] - cmx);
        }
        float s = (s0 + s1) + (s2 + s3);
        if (cmx > E) { M = M * exp2f(E - cmx) + s; E = cmx; }
        else         { M += s * exp2f(cmx - E); }
    }
}

__global__ __launch_bounds__(256) void pass_kernel(int dir) {
    const float* __restrict__ ZA   = dir ? g_DmT : g_Dm;
    const float* __restrict__ zo   = dir ? g_zr  : g_zc;
    double* __restrict__      vec  = dir ? g_c   : g_r;
    float* __restrict__       zvec = dir ? g_zc  : g_zr;
    const float k1 = g_k1, k2 = g_k2;

    __shared__ float sM[8], sE[8];
    const int tid = threadIdx.x;
    const int lane = tid & 31;
    const int wid = tid >> 5;
    const int rloc = wid >> 1;
    const int half = wid & 1;
    const int i = (blockIdx.x << 2) + rloc;
    const float* Arow = ZA + (size_t)i * NK;
    const float4* c4 = (const float4*)zo;
    const int base8 = half << 9;          // float8 offset: 0 or 512

    float M = 0.f, E = -3.4e38f;
    if (i < PERSIST_ROWS) pass_accum<true>(Arow, c4, base8, lane, k1, M, E);
    else                  pass_accum<false>(Arow, c4, base8, lane, k1, M, E);

    for (int o = 16; o; o >>= 1) {
        float oe = __shfl_down_sync(0xffffffffu, E, o);
        float om = __shfl_down_sync(0xffffffffu, M, o);
        if (oe > E) { M = M * exp2f(E - oe) + om; E = oe; }
        else        { M += om * exp2f(oe - E); }
    }
    if (lane == 0) { sM[wid] = M; sE[wid] = E; }
    __syncthreads();
    if (half == 0 && lane == 0) {
        float oM = sM[wid + 1], oE = sE[wid + 1];
        if (oE > E) { M = M * exp2f(E - oE) + oM; E = oE; }
        else        { M += oM * exp2f(oE - E); }
        float Ei = floorf(E);
        double y = ldexp((double)(M * exp2f(E - Ei)), (int)Ei);
        double v = vec[i];
        double vn = v / ((v * y) + 1e-8) / 8192.0;
        vec[i] = vn;
        zvec[i] = k2 + log2_of_double(vn);
    }
}

// ---------------- probs + argmax: 2 warps per row, 256-bit L2-hinted loads ----------------
template<bool KEEP>
__device__ __forceinline__ void probs_body(const float* __restrict__ Arow,
                                           const float4* __restrict__ c4,
                                           float4* __restrict__ o4,
                                           int base8, int lane, float k1, float lR,
                                           float& best, int& bj) {
#pragma unroll 4
    for (int v = 0; v < 16; v++) {
        int j8 = base8 + (v << 5) + lane;
        float4 alo, ahi;
        ld8h<KEEP>(Arow + (size_t)j8 * 8, alo, ahi);
        float4 clo = __ldg(&c4[2 * j8]);
        float4 chi = __ldg(&c4[2 * j8 + 1]);
        float t0 = fmaf(alo.x, k1, clo.x), t1 = fmaf(alo.y, k1, clo.y);
        float t2 = fmaf(alo.z, k1, clo.z), t3 = fmaf(alo.w, k1, clo.w);
        float t4 = fmaf(ahi.x, k1, chi.x), t5 = fmaf(ahi.y, k1, chi.y);
        float t6 = fmaf(ahi.z, k1, chi.z), t7 = fmaf(ahi.w, k1, chi.w);
        o4[2 * j8]     = make_float4(exp2f(t0 + lR), exp2f(t1 + lR), exp2f(t2 + lR), exp2f(t3 + lR));
        o4[2 * j8 + 1] = make_float4(exp2f(t4 + lR), exp2f(t5 + lR), exp2f(t6 + lR), exp2f(t7 + lR));
        int jb = j8 << 3;
        if (t0 > best) { best = t0; bj = jb; }
        if (t1 > best) { best = t1; bj = jb + 1; }
        if (t2 > best) { best = t2; bj = jb + 2; }
        if (t3 > best) { best = t3; bj = jb + 3; }
        if (t4 > best) { best = t4; bj = jb + 4; }
        if (t5 > best) { best = t5; bj = jb + 5; }
        if (t6 > best) { best = t6; bj = jb + 6; }
        if (t7 > best) { best = t7; bj = jb + 7; }
    }
}

__global__ __launch_bounds__(256) void probs_kernel(float* __restrict__ out_probs,
                                                    float* __restrict__ out_idx) {
    __shared__ float sB[8];
    __shared__ int sJ[8];
    const int tid = threadIdx.x;
    const int lane = tid & 31;
    const int wid = tid >> 5;
    const int rloc = wid >> 1;
    const int half = wid & 1;
    const int i = (blockIdx.x << 2) + rloc;
    const float k1 = g_k1;
    const float lR = log2_of_double(8192.0 * g_r[i]);
    const float* Arow = g_Dm + (size_t)i * NK;
    const float4* c4 = (const float4*)g_zc;
    float4* o4 = (float4*)(out_probs + (size_t)i * NK);
    const int base8 = half << 9;

    float best = -3.4e38f; int bj = 0x7FFFFFFF;
    if (i < PERSIST_ROWS) probs_body<true>(Arow, c4, o4, base8, lane, k1, lR, best, bj);
    else                  probs_body<false>(Arow, c4, o4, base8, lane, k1, lR, best, bj);

    for (int o = 16; o; o >>= 1) {
        float ov = __shfl_down_sync(0xffffffffu, best, o);
        int oi = __shfl_down_sync(0xffffffffu, bj, o);
        if (ov > best || (ov == best && oi < bj)) { best = ov; bj = oi; }
    }
    if (lane == 0) { sB[wid] = best; sJ[wid] = bj; }
    __syncthreads();
    if (half == 0 && lane == 0) {
        float ov = sB[wid + 1]; int oi = sJ[wid + 1];
        if (ov > best || (ov == best && oi < bj)) { best = ov; bj = oi; }
        g_idx[i] = bj;
        out_idx[i] = (float)bj;
    }
}

// ---------------- epilogue ----------------
__global__ __launch_bounds__(128) void epilogue_kernel(const float* __restrict__ X,
                                                       const float* __restrict__ C,
                                                       float* __restrict__ qh,
                                                       float* __restrict__ qs,
                                                       float* __restrict__ loss) {
    int i = blockIdx.x;
    int idx = g_idx[i];
    const float4* cb = (const float4*)(C + (size_t)idx * ND);
    const float4* xr = (const float4*)(X + (size_t)i * ND);
    float4* oh = (float4*)(qh + (size_t)i * ND);
    float4* os = (float4*)(qs + (size_t)i * ND);
    int t = threadIdx.x;
    float4 c4 = cb[t];
    float4 x4 = xr[t];
    oh[t] = c4;
    float dx = c4.x - x4.x, dy = c4.y - x4.y, dz = c4.z - x4.z, dw = c4.w - x4.w;
    os[t] = make_float4(dx + x4.x, dy + x4.y, dz + x4.z, dw + x4.w);
    double s = (double)dx * dx + (double)dy * dy + (double)dz * dz + (double)dw * dw;
    for (int o = 16; o; o >>= 1) s += __shfl_down_sync(0xffffffffu, s, o);
    __shared__ double sm[4];
    if ((t & 31) == 0) sm[t >> 5] = s;
    __syncthreads();
    if (t == 0) {
        double tot = (sm[0] + sm[1]) + (sm[2] + sm[3]);
        float cl = (float)(tot / (double)ND);
        loss[i] = cl + 0.25f * cl;
    }
}

// ---------------- launch ----------------
extern "C" void kernel_launch(void* const* d_in, const int* in_sizes, int n_in,
                              void* d_out, int out_size) {
    const float* X = (const float*)d_in[0];
    const float* C = (const float*)d_in[1];
    float* out = (float*)d_out;
    float* o_qh    = out;
    float* o_qs    = out + (size_t)NB * ND;
    float* o_idx   = out + 2ULL * NB * ND;
    float* o_probs = o_idx + NB;
    float* o_loss  = o_probs + NM;

    cudaFuncSetAttribute(mma_gemm_kernel, cudaFuncAttributeMaxDynamicSharedMemorySize,
                         3 * STAGE_BYTES);

    reset_kernel<<<1, 32>>>();
    norms_kernel<<<dim3(NB, 2), 128>>>(X, C);
    split_kernel<<<16384, 256>>>(X, C);
    mma_gemm_kernel<<<dim3(64, 64), 256, 3 * STAGE_BYTES>>>();
    finalize_kernel<<<1, 1>>>();
    transpose_kernel<<<dim3(128, 128), 256>>>();
    reduceS_kernel<<<1, 1024>>>();
    init_rc_kernel<<<32, 256>>>();
    for (int it = 0; it < 50; it++) {
        pass_kernel<<<2048, 256>>>(0);
        pass_kernel<<<2048, 256>>>(1);
    }
    probs_kernel<<<2048, 256>>>(o_probs, o_idx);
    epilogue_kernel<<<NB, 128>>>(X, C, o_qh, o_qs, o_loss);
}